// round 5
// baseline (speedup 1.0000x reference)
#include <cuda_runtime.h>
#include <cuda_bf16.h>
#include <cstdint>

#define BATCH 4096
#define SEQ   24
#define TT    32
#define VOC   120
#define EMB   128
#define HE    512
#define HD    512
#define START_TOKEN 2
#define NCOMB 2560   // 4*HD gates + HD q

typedef __nv_bfloat16 bf16;
typedef unsigned int u32;

// ---------------- device scratch ----------------
__device__ __align__(256) bf16 g_ench[(size_t)BATCH * SEQ * HE];
__device__ __align__(256) bf16 g_encl[(size_t)BATCH * SEQ * HE];
__device__ __align__(256) bf16 g_efh[(size_t)BATCH * HE];
__device__ __align__(256) bf16 g_efl[(size_t)BATCH * HE];
__device__ __align__(256) float g_encproj[(size_t)BATCH * SEQ * HD];
__device__ __align__(256) float g_ctxw[(size_t)BATCH * SEQ * HD];
__device__ __align__(256) float g_encw[(size_t)BATCH * SEQ];
__device__ __align__(256) float g_embproj[(size_t)VOC * 4 * HD];
// weights (bf16 hi/lo)
__device__ __align__(256) bf16 g_wcombh[(size_t)NCOMB * HD];  // [W_hh ; W_dec^T]
__device__ __align__(256) bf16 g_wcombl[(size_t)NCOMB * HD];
__device__ __align__(256) float g_bcomb[NCOMB];
__device__ __align__(256) bf16 g_weh[(size_t)HE * HD];
__device__ __align__(256) bf16 g_wel[(size_t)HE * HD];
__device__ __align__(256) bf16 g_waph[(size_t)HD * (HD + HE)];
__device__ __align__(256) bf16 g_wapl[(size_t)HD * (HD + HE)];
__device__ __align__(256) bf16 g_woch[(size_t)121 * HD];      // [W_out; w_copy_ah]
__device__ __align__(256) bf16 g_wocl[(size_t)121 * HD];
__device__ __align__(256) float g_boc[121];
__device__ __align__(256) bf16 g_wih[(size_t)HD * HE];
__device__ __align__(256) bf16 g_wil[(size_t)HD * HE];
// activations
__device__ __align__(256) bf16 g_hh[(size_t)BATCH * HD];
__device__ __align__(256) bf16 g_hl[(size_t)BATCH * HD];
__device__ __align__(256) float g_c[(size_t)BATCH * HD];
__device__ __align__(256) float g_comb[(size_t)BATCH * NCOMB];
__device__ __align__(256) float g_ahpre[(size_t)BATCH * HD];
__device__ __align__(256) bf16 g_ahh_all[(size_t)TT * BATCH * HD];
__device__ __align__(256) bf16 g_ahl_all[(size_t)TT * BATCH * HD];
__device__ __align__(256) float g_logits_all[(size_t)TT * BATCH * 121];
__device__ __align__(256) float g_ctxdot[(size_t)TT * BATCH];

// ---------------- math helpers ----------------
__device__ __forceinline__ float tanh_fast(float x) {
    float e = __expf(2.0f * x);
    return 1.0f - 2.0f / (e + 1.0f);
}
__device__ __forceinline__ float sigmoid_fast(float x) {
    return 1.0f / (1.0f + __expf(-x));
}
__device__ __forceinline__ void split2(float v, bf16* hi, bf16* lo) {
    bf16 h = __float2bfloat16(v);
    *hi = h;
    *lo = __float2bfloat16(v - __bfloat162float(h));
}

// ---------------- PTX helpers ----------------
__device__ __forceinline__ u32 smem_u32(const void* p) {
    u32 a;
    asm("{ .reg .u64 t; cvta.to.shared.u64 t, %1; cvt.u32.u64 %0, t; }"
        : "=r"(a) : "l"(p));
    return a;
}
__device__ __forceinline__ void cp16(u32 d, const void* s, u32 sz) {
    asm volatile("cp.async.cg.shared.global [%0], [%1], 16, %2;"
                 :: "r"(d), "l"(s), "r"(sz) : "memory");
}
__device__ __forceinline__ void cp_commit() {
    asm volatile("cp.async.commit_group;" ::: "memory");
}
template<int N>
__device__ __forceinline__ void cp_wait() {
    asm volatile("cp.async.wait_group %0;" :: "n"(N) : "memory");
}
__device__ __forceinline__ void ldsm_x4(u32* r, u32 a) {
    asm volatile("ldmatrix.sync.aligned.m8n8.x4.shared.b16 {%0,%1,%2,%3}, [%4];"
                 : "=r"(r[0]), "=r"(r[1]), "=r"(r[2]), "=r"(r[3]) : "r"(a));
}
__device__ __forceinline__ void mma_bf16(float* c, const u32* a, const u32* b) {
    asm volatile(
        "mma.sync.aligned.m16n8k16.row.col.f32.bf16.bf16.f32 "
        "{%0,%1,%2,%3}, {%4,%5,%6,%7}, {%8,%9}, {%0,%1,%2,%3};"
        : "+f"(c[0]), "+f"(c[1]), "+f"(c[2]), "+f"(c[3])
        : "r"(a[0]), "r"(a[1]), "r"(a[2]), "r"(a[3]), "r"(b[0]), "r"(b[1]));
}

// ---------------- mma.sync split-bf16 GEMM ----------------
// C[M,*] = A[M,K] * B[N,K]^T (+bias)(+Cadd)(opt tanh / bf16 split-out)
// M%128==0, K%32==0, strides %8==0. Grid ((n tiles), M/128); 256 thr.
// bn offset by noff tiles (partial-N launches into a wider C).

template<int BN, bool DOTANH, bool SPLITOUT>
__global__ __launch_bounds__(256, 2)
void mma_gemm_k(const bf16* __restrict__ Ah_, const bf16* __restrict__ Al_,
                int lda,
                const bf16* __restrict__ Bh, const bf16* __restrict__ Bl, int ldb,
                const float* __restrict__ bias,
                const float* __restrict__ Cadd,
                float* __restrict__ C, bf16* __restrict__ Ch, bf16* __restrict__ Cl,
                int K, int Nreal, int noff)
{
    constexpr int BUFB = 20480 + BN * 160;
    constexpr int BLO  = BN * 80;
    constexpr int NTN  = BN / 16;

    extern __shared__ char smem[];
    const u32 sb = smem_u32(smem);
    const int tid = threadIdx.x, lane = tid & 31, wid = tid >> 5;
    const int bm = blockIdx.y * 128, bn = (blockIdx.x + noff) * BN;
    const int wm = (wid >> 1) * 32, wn = (wid & 1) * (BN / 2);

    float acc[2][NTN][4];
#pragma unroll
    for (int m = 0; m < 2; m++)
#pragma unroll
        for (int n = 0; n < NTN; n++)
#pragma unroll
            for (int j = 0; j < 4; j++) acc[m][n][j] = 0.0f;

    const int nch = K / 32;

    auto stage = [&](int c) {
        const int kt = c * 32;
        const u32 bufb = sb + (u32)(c & 1) * BUFB;
#pragma unroll
        for (int p = 0; p < 2; p++) {
            int v = tid + p * 256, row = v >> 2, g = v & 3;
            size_t go = (size_t)(bm + row) * lda + kt + g * 8;
            u32 sa = bufb + row * 80 + g * 16;
            cp16(sa, Ah_ + go, 16);
            cp16(sa + 10240, Al_ + go, 16);
        }
#pragma unroll
        for (int p = 0; p < BN / 64; p++) {
            int v = tid + p * 256, row = v >> 2, g = v & 3;
            int n = bn + row;
            int na = (n < Nreal) ? n : (Nreal - 1);
            u32 sz = (n < Nreal) ? 16u : 0u;
            size_t go = (size_t)na * ldb + kt + g * 8;
            u32 sa = bufb + 20480 + row * 80 + g * 16;
            cp16(sa, Bh + go, sz);
            cp16(sa + BLO, Bl + go, sz);
        }
    };

    stage(0);
    cp_commit();

    for (int c = 0; c < nch; c++) {
        if (c + 1 < nch) {
            stage(c + 1);
            cp_commit();
            cp_wait<1>();
        } else {
            cp_wait<0>();
        }
        __syncthreads();

        const u32 bufb = sb + (u32)(c & 1) * BUFB;
#pragma unroll
        for (int k2 = 0; k2 < 2; k2++) {
            const u32 kb = k2 * 32;
            const u32 aaddr0 = bufb + (wm + (lane & 15)) * 80 + kb + (lane >> 4) * 16;
            const u32 aaddr1 = aaddr0 + 16 * 80;
            u32 ah[2][4], al[2][4];
            ldsm_x4(ah[0], aaddr0);
            ldsm_x4(ah[1], aaddr1);
            ldsm_x4(al[0], aaddr0 + 10240);
            ldsm_x4(al[1], aaddr1 + 10240);
            const u32 bb0 = bufb + 20480 +
                (wn + (lane & 7) + ((lane >> 4) & 1) * 8) * 80 +
                kb + ((lane >> 3) & 1) * 16;
#pragma unroll
            for (int nt2 = 0; nt2 < NTN / 2; nt2++) {
                u32 ba = bb0 + nt2 * 16 * 80;
                u32 bh4[4], bl4[4];
                ldsm_x4(bh4, ba);
                ldsm_x4(bl4, ba + BLO);
#pragma unroll
                for (int half = 0; half < 2; half++) {
                    int nt = nt2 * 2 + half;
                    const u32* bh = bh4 + half * 2;
                    const u32* bl = bl4 + half * 2;
#pragma unroll
                    for (int m = 0; m < 2; m++) {
                        mma_bf16(acc[m][nt], ah[m], bh);
                        mma_bf16(acc[m][nt], ah[m], bl);
                        mma_bf16(acc[m][nt], al[m], bh);
                    }
                }
            }
        }
        __syncthreads();
    }

    auto emit = [&](int r, int n, float v) {
        if (n >= Nreal) return;
        size_t o = (size_t)r * Nreal + n;
        if (bias) v += bias[n];
        if (Cadd) v += Cadd[o];
        if (DOTANH) v = tanh_fast(v);
        if (C) C[o] = v;
        if (SPLITOUT) split2(v, &Ch[o], &Cl[o]);
    };
#pragma unroll
    for (int m = 0; m < 2; m++) {
        int r0 = bm + wm + m * 16 + (lane >> 2);
#pragma unroll
        for (int nt = 0; nt < NTN; nt++) {
            int gn = bn + wn + nt * 8 + (lane & 3) * 2;
            emit(r0,     gn,     acc[m][nt][0]);
            emit(r0,     gn + 1, acc[m][nt][1]);
            emit(r0 + 8, gn,     acc[m][nt][2]);
            emit(r0 + 8, gn + 1, acc[m][nt][3]);
        }
    }
}

// ---------------- prep kernels ----------------
__global__ void split_arr_k(const float* __restrict__ src,
                            bf16* __restrict__ h, bf16* __restrict__ l, size_t n)
{
    for (size_t i = (size_t)blockIdx.x * blockDim.x + threadIdx.x; i < n;
         i += (size_t)gridDim.x * blockDim.x)
        split2(src[i], &h[i], &l[i]);
}

__global__ void transpose_split_k(const float* __restrict__ src,  // [K][N]
                                  bf16* __restrict__ h, bf16* __restrict__ l,
                                  int Kd, int Nd)
{
    size_t n = (size_t)Kd * Nd;
    for (size_t i = (size_t)blockIdx.x * blockDim.x + threadIdx.x; i < n;
         i += (size_t)gridDim.x * blockDim.x) {
        int k = (int)(i / Nd), nn = (int)(i % Nd);
        split2(src[i], &h[(size_t)nn * Kd + k], &l[(size_t)nn * Kd + k]);
    }
}

// combined recurrent weight: rows 0..2047 W_hh; rows 2048..2559 W_dec^T
__global__ void prep_comb_k(const float* __restrict__ W_hh,
                            const float* __restrict__ W_dec,
                            const float* __restrict__ b_attn,
                            bf16* __restrict__ wh, bf16* __restrict__ wl,
                            float* __restrict__ bc)
{
    size_t n = (size_t)NCOMB * HD;
    for (size_t i = (size_t)blockIdx.x * blockDim.x + threadIdx.x; i < n;
         i += (size_t)gridDim.x * blockDim.x) {
        int row = (int)(i / HD), k = (int)(i % HD);
        float v = (row < 4 * HD) ? W_hh[(size_t)row * HD + k]
                                 : W_dec[(size_t)k * HD + (row - 4 * HD)];
        split2(v, &wh[i], &wl[i]);
        if (i < NCOMB) bc[i] = (i < 4 * HD) ? 0.0f : b_attn[i - 4 * HD];
    }
}

__global__ void embproj_k(const float* __restrict__ embed,
                          const float* __restrict__ W_ih,
                          const float* __restrict__ b_ih,
                          const float* __restrict__ b_hh,
                          float* __restrict__ ep)
{
    int v = blockIdx.y;
    int j = blockIdx.x * 128 + threadIdx.x;
    __shared__ float em[EMB];
    if (threadIdx.x < EMB) em[threadIdx.x] = embed[(size_t)v * EMB + threadIdx.x];
    __syncthreads();
    float acc = b_ih[j] + b_hh[j];
    const float* w = W_ih + (size_t)j * EMB;
#pragma unroll 8
    for (int k = 0; k < EMB; k++) acc += em[k] * w[k];
    ep[(size_t)v * 4 * HD + j] = acc;
}

__global__ void prep_outw_k(const float* __restrict__ W_out,
                            const float* __restrict__ b_out,
                            const float* __restrict__ w_copy,
                            const float* __restrict__ b_copy,
                            bf16* __restrict__ wh, bf16* __restrict__ wl,
                            float* __restrict__ bo)
{
    size_t n = (size_t)121 * HD;
    for (size_t i = (size_t)blockIdx.x * blockDim.x + threadIdx.x; i < n;
         i += (size_t)gridDim.x * blockDim.x) {
        int row = (int)(i / HD), k = (int)(i % HD);
        float v = (row < VOC) ? W_out[(size_t)row * HD + k] : w_copy[k];
        split2(v, &wh[i], &wl[i]);
        if (i < 121) bo[i] = (i < VOC) ? b_out[i] : b_copy[0];
    }
}

// encw[r] = enc_row_r . w_copy[512:1024]   (one 128-thread block per row)
__global__ void encw_k(const float* __restrict__ enc,
                       const float* __restrict__ w_copy,
                       float* __restrict__ encw)
{
    int r = blockIdx.x;
    int tid = threadIdx.x;
    __shared__ float red[128];
    const float* row = enc + (size_t)r * HE;
    float acc = 0.f;
    for (int k = tid; k < HE; k += 128) acc += row[k] * w_copy[HD + k];
    red[tid] = acc;
    __syncthreads();
    for (int s2 = 64; s2; s2 >>= 1) {
        if (tid < s2) red[tid] += red[tid + s2];
        __syncthreads();
    }
    if (tid == 0) encw[r] = red[0];
}

__global__ void zero_c_k(float* __restrict__ c)
{
    size_t i = (size_t)blockIdx.x * blockDim.x + threadIdx.x;
    if (i < (size_t)BATCH * HD) c[i] = 0.0f;
}

__global__ void lstm_cell_k(const float* __restrict__ comb,  // stride NCOMB
                            const float* __restrict__ ep,
                            const int* __restrict__ tgt,
                            bf16* __restrict__ hh, bf16* __restrict__ hl,
                            float* __restrict__ c, int t)
{
    size_t i = (size_t)blockIdx.x * blockDim.x + threadIdx.x;
    if (i >= (size_t)BATCH * HD) return;
    int b = (int)(i / HD);
    int d = (int)(i % HD);
    int tok = (t == 0) ? START_TOKEN : tgt[(size_t)b * TT + (t - 1)];
    const float* g = comb + (size_t)b * NCOMB;
    const float* e = ep + (size_t)tok * 4 * HD;
    float ig = sigmoid_fast(g[d] + e[d]);
    float fg = sigmoid_fast(g[HD + d] + e[HD + d]);
    float gg = tanh_fast(g[2 * HD + d] + e[2 * HD + d]);
    float og = sigmoid_fast(g[3 * HD + d] + e[3 * HD + d]);
    float cn = fg * c[i] + ig * gg;
    c[i] = cn;
    float hn = og * tanh_fast(cn);
    split2(hn, &hh[i], &hl[i]);
}

// block per batch row; 128 threads
__global__ void attn_k(const float* __restrict__ encproj,
                       const float* __restrict__ ctxw,
                       const float* __restrict__ encw,
                       const float* __restrict__ comb,   // q at cols [2048,2560)
                       const float* __restrict__ v_attn,
                       float* __restrict__ attn_out,
                       float* __restrict__ ahpre,
                       float* __restrict__ ctxdot,
                       int t)
{
    int b = blockIdx.x;
    int tid = threadIdx.x;
    __shared__ float qsh[HD];
    __shared__ float vsh[HD];
    __shared__ float sc[SEQ];
    __shared__ float aprob[SEQ];

    for (int d = tid; d < HD; d += 128) {
        qsh[d] = comb[(size_t)b * NCOMB + 4 * HD + d];
        vsh[d] = v_attn[d];
    }
    __syncthreads();

    int w = tid >> 5, lane = tid & 31;
    const float* ep = encproj + (size_t)b * SEQ * HD;
    for (int s = w; s < SEQ; s += 4) {
        float acc = 0.f;
        const float* row = ep + (size_t)s * HD;
        for (int d = lane; d < HD; d += 32)
            acc += tanh_fast(row[d] + qsh[d]) * vsh[d];
#pragma unroll
        for (int o = 16; o; o >>= 1) acc += __shfl_xor_sync(0xffffffffu, acc, o);
        if (lane == 0) sc[s] = acc;
    }
    __syncthreads();

    if (tid < 32) {
        float v = (tid < SEQ) ? sc[tid] : -1e30f;
        float m = v;
#pragma unroll
        for (int o = 16; o; o >>= 1) m = fmaxf(m, __shfl_xor_sync(0xffffffffu, m, o));
        float e = (tid < SEQ) ? __expf(v - m) : 0.f;
        float sum = e;
#pragma unroll
        for (int o = 16; o; o >>= 1) sum += __shfl_xor_sync(0xffffffffu, sum, o);
        float a = e / sum;
        float cd = 0.f;
        if (tid < SEQ) {
            aprob[tid] = a;
            attn_out[(size_t)b * TT * SEQ + (size_t)t * SEQ + tid] = a;
            cd = a * encw[(size_t)b * SEQ + tid];
        }
#pragma unroll
        for (int o = 16; o; o >>= 1) cd += __shfl_xor_sync(0xffffffffu, cd, o);
        if (tid == 0) ctxdot[(size_t)t * BATCH + b] = cd;
    }
    __syncthreads();

    // ahpre[b][d] = sum_s aprob[s] * ctxw[b,s,d]
    const float* cw = ctxw + (size_t)b * SEQ * HD;
    for (int d = tid; d < HD; d += 128) {
        float acc = 0.f;
#pragma unroll
        for (int s = 0; s < SEQ; s++)
            acc += aprob[s] * cw[(size_t)s * HD + d];
        ahpre[(size_t)b * HD + d] = acc;
    }
}

// one block per (t,b): softmax + pointer-generator mix
__global__ void out2_k(const float* __restrict__ logits_all,  // [T*B][121]
                       const float* __restrict__ ctxdot,      // [T*B]
                       const int* __restrict__ input_char_ids,
                       const float* __restrict__ attn_base,
                       float* __restrict__ outputs)
{
    int row = blockIdx.x;
    int t = row >> 12;
    int b = row & 4095;
    int tid = threadIdx.x;
    __shared__ float red[128];
    __shared__ float cbuf[VOC];
    __shared__ float psh;

    const float* lrow = logits_all + (size_t)row * 121;
    if (tid == 0) psh = sigmoid_fast(lrow[120] + ctxdot[row]);
    if (tid < VOC) cbuf[tid] = 0.f;
    __syncthreads();

    if (tid < SEQ) {
        int id = input_char_ids[(size_t)b * SEQ + tid];
        float a = attn_base[(size_t)b * TT * SEQ + (size_t)t * SEQ + tid];
        atomicAdd(&cbuf[id], a);
    }

    float lg = (tid < VOC) ? lrow[tid] : -1e30f;
    red[tid] = lg;
    __syncthreads();
    for (int s2 = 64; s2; s2 >>= 1) {
        if (tid < s2) red[tid] = fmaxf(red[tid], red[tid + s2]);
        __syncthreads();
    }
    float m = red[0];
    __syncthreads();
    float e = (tid < VOC) ? __expf(lg - m) : 0.f;
    red[tid] = e;
    __syncthreads();
    for (int s2 = 64; s2; s2 >>= 1) {
        if (tid < s2) red[tid] += red[tid + s2];
        __syncthreads();
    }
    float sum = red[0];
    __syncthreads();

    if (tid < VOC) {
        float p = psh;
        outputs[(size_t)b * TT * VOC + (size_t)t * VOC + tid] =
            (1.0f - p) * (e / sum) + p * cbuf[tid];
    }
}

// ---------------- host ----------------
#define SYM(p, s) cudaGetSymbolAddress((void**)&(p), s)
#define SM128 81920
#define SM64  61440

extern "C" void kernel_launch(void* const* d_in, const int* in_sizes, int n_in,
                              void* d_out, int out_size)
{
    (void)in_sizes; (void)n_in; (void)out_size;
    const float* enc        = (const float*)d_in[0];
    const float* enc_final  = (const float*)d_in[1];
    const int*   tgt        = (const int*)d_in[2];
    const int*   input_ids  = (const int*)d_in[3];
    const float* embed      = (const float*)d_in[4];
    const float* W_init     = (const float*)d_in[5];
    const float* b_init     = (const float*)d_in[6];
    const float* W_ih       = (const float*)d_in[7];
    const float* W_hh       = (const float*)d_in[8];
    const float* b_ih       = (const float*)d_in[9];
    const float* b_hh       = (const float*)d_in[10];
    const float* W_enc_attn = (const float*)d_in[11];
    const float* W_dec_attn = (const float*)d_in[12];
    const float* b_attn     = (const float*)d_in[13];
    const float* v_attn     = (const float*)d_in[14];
    const float* W_ap       = (const float*)d_in[15];
    const float* b_ap       = (const float*)d_in[16];
    const float* W_out      = (const float*)d_in[17];
    const float* b_out      = (const float*)d_in[18];
    const float* w_copy     = (const float*)d_in[19];
    const float* b_copy     = (const float*)d_in[20];

    float* out = (float*)d_out;
    float* outputs   = out;
    float* attn_base = out + (size_t)BATCH * TT * VOC;

    bf16 *ench, *encl, *efh, *efl;
    bf16 *wcombh, *wcombl, *weh, *wel, *waph, *wapl, *woch, *wocl, *wih, *wil;
    bf16 *hh, *hl, *ahh, *ahl;
    float *encproj, *ctxwp, *encw, *embproj, *bcomb, *boc, *cst;
    float *comb, *ahpre, *logits_all, *ctxdot;
    SYM(ench, g_ench); SYM(encl, g_encl);
    SYM(efh, g_efh);   SYM(efl, g_efl);
    SYM(encproj, g_encproj); SYM(ctxwp, g_ctxw); SYM(encw, g_encw);
    SYM(embproj, g_embproj);
    SYM(wcombh, g_wcombh); SYM(wcombl, g_wcombl); SYM(bcomb, g_bcomb);
    SYM(weh, g_weh);   SYM(wel, g_wel);
    SYM(waph, g_waph); SYM(wapl, g_wapl);
    SYM(woch, g_woch); SYM(wocl, g_wocl); SYM(boc, g_boc);
    SYM(wih, g_wih);   SYM(wil, g_wil);
    SYM(hh, g_hh);     SYM(hl, g_hl);
    SYM(cst, g_c);     SYM(comb, g_comb); SYM(ahpre, g_ahpre);
    SYM(ahh, g_ahh_all); SYM(ahl, g_ahl_all);
    SYM(logits_all, g_logits_all); SYM(ctxdot, g_ctxdot);

    cudaFuncSetAttribute(mma_gemm_k<128, false, false>,
                         cudaFuncAttributeMaxDynamicSharedMemorySize, SM128);
    cudaFuncSetAttribute(mma_gemm_k<64, false, true>,
                         cudaFuncAttributeMaxDynamicSharedMemorySize, SM64);
    cudaFuncSetAttribute(mma_gemm_k<64, true, true>,
                         cudaFuncAttributeMaxDynamicSharedMemorySize, SM64);

    // ---- prep ----
    split_arr_k<<<4096, 256>>>(enc, ench, encl, (size_t)BATCH * SEQ * HE);
    split_arr_k<<<2048, 256>>>(enc_final, efh, efl, (size_t)BATCH * HE);
    embproj_k<<<dim3(16, VOC), 128>>>(embed, W_ih, b_ih, b_hh, embproj);
    prep_comb_k<<<2048, 256>>>(W_hh, W_dec_attn, b_attn, wcombh, wcombl, bcomb);
    transpose_split_k<<<1024, 256>>>(W_enc_attn, weh, wel, HE, HD);
    split_arr_k<<<1024, 256>>>(W_ap, waph, wapl, (size_t)HD * (HD + HE));
    prep_outw_k<<<256, 256>>>(W_out, b_out, w_copy, b_copy, woch, wocl, boc);
    split_arr_k<<<1024, 256>>>(W_init, wih, wil, (size_t)HD * HE);
    encw_k<<<BATCH * SEQ, 128>>>(enc, w_copy, encw);
    zero_c_k<<<(BATCH * HD + 255) / 256, 256>>>(cst);

    // h0 = enc_final @ W_init^T + b_init
    mma_gemm_k<64, false, true><<<dim3(8, 32), 256, SM64>>>(
        efh, efl, HE, wih, wil, HE, b_init, nullptr,
        nullptr, hh, hl, HE, HD, 0);
    // enc_proj = enc @ W_enc_attn
    mma_gemm_k<128, false, false><<<dim3(4, 768), 256, SM128>>>(
        ench, encl, HE, weh, wel, HE, nullptr, nullptr,
        encproj, nullptr, nullptr, HE, HD, 0);
    // ctxw = enc @ W_ap[:,512:]^T
    mma_gemm_k<128, false, false><<<dim3(4, 768), 256, SM128>>>(
        ench, encl, HE, waph + HD, wapl + HD, HD + HE, nullptr, nullptr,
        ctxwp, nullptr, nullptr, HE, HD, 0);
    // gates_0 = h0 @ W_hh^T  (cols 0..2047 of comb)
    mma_gemm_k<128, false, false><<<dim3(16, 32), 256, SM128>>>(
        hh, hl, HD, wcombh, wcombl, HD, bcomb, nullptr,
        comb, nullptr, nullptr, HD, NCOMB, 0);

    for (int t = 0; t < TT; t++) {
        lstm_cell_k<<<(BATCH * HD + 255) / 256, 256>>>(
            comb, embproj, tgt, hh, hl, cst, t);
        // comb = h_t @ [W_hh ; W_dec^T]^T : gates_{t+1} (cols<2048) + q_t
        if (t < TT - 1) {
            mma_gemm_k<128, false, false><<<dim3(20, 32), 256, SM128>>>(
                hh, hl, HD, wcombh, wcombl, HD, bcomb, nullptr,
                comb, nullptr, nullptr, HD, NCOMB, 0);
        } else {
            mma_gemm_k<128, false, false><<<dim3(4, 32), 256, SM128>>>(
                hh, hl, HD, wcombh, wcombl, HD, bcomb, nullptr,
                comb, nullptr, nullptr, HD, NCOMB, 16);
        }
        attn_k<<<BATCH, 128>>>(encproj, ctxwp, encw, comb, v_attn,
                               attn_base, ahpre, ctxdot, t);
        // ah = tanh(h @ W_ap[:, :512]^T + ahpre + b_ap) -> split slice t
        mma_gemm_k<64, true, true><<<dim3(8, 32), 256, SM64>>>(
            hh, hl, HD, waph, wapl, HD + HE, b_ap, ahpre,
            nullptr,
            ahh + (size_t)t * BATCH * HD, ahl + (size_t)t * BATCH * HD,
            HD, HD, 0);
    }

    // deferred logits+copy GEMM: M = T*B, N = 121, K = 512
    mma_gemm_k<128, false, false><<<dim3(1, (TT * BATCH) / 128), 256, SM128>>>(
        ahh, ahl, HD, woch, wocl, HD, boc, nullptr,
        logits_all, nullptr, nullptr, HD, 121, 0);
    out2_k<<<TT * BATCH, 128>>>(logits_all, ctxdot, input_ids, attn_base, outputs);
}

// round 6
// speedup vs baseline: 1.4907x; 1.4907x over previous
#include <cuda_runtime.h>
#include <cuda_bf16.h>
#include <cstdint>

#define BATCH 4096
#define SEQ   24
#define TT    32
#define VOC   120
#define EMB   128
#define HE    512
#define HD    512
#define START_TOKEN 2
#define NCOMB 2560   // 2048 interleaved gates + 512 q

typedef __nv_bfloat16 bf16;
typedef unsigned int u32;

// ---------------- device scratch ----------------
__device__ __align__(256) bf16 g_ench[(size_t)BATCH * SEQ * HE];
__device__ __align__(256) bf16 g_encl[(size_t)BATCH * SEQ * HE];
__device__ __align__(256) bf16 g_efh[(size_t)BATCH * HE];
__device__ __align__(256) bf16 g_efl[(size_t)BATCH * HE];
__device__ __align__(256) float g_encproj[(size_t)BATCH * SEQ * HD];
__device__ __align__(256) float g_ctxw[(size_t)BATCH * SEQ * HD];
__device__ __align__(256) float g_encw[(size_t)BATCH * SEQ];
__device__ __align__(256) float g_embproj[(size_t)VOC * 4 * HD];   // [tok][4d+g]
// weights (bf16 hi/lo)
__device__ __align__(256) bf16 g_wcombh[(size_t)NCOMB * HD];
__device__ __align__(256) bf16 g_wcombl[(size_t)NCOMB * HD];
__device__ __align__(256) float g_bcomb[NCOMB];
__device__ __align__(256) bf16 g_weh[(size_t)HE * HD];
__device__ __align__(256) bf16 g_wel[(size_t)HE * HD];
__device__ __align__(256) bf16 g_waph[(size_t)HD * (HD + HE)];
__device__ __align__(256) bf16 g_wapl[(size_t)HD * (HD + HE)];
__device__ __align__(256) bf16 g_woch[(size_t)121 * HD];
__device__ __align__(256) bf16 g_wocl[(size_t)121 * HD];
__device__ __align__(256) float g_boc[121];
__device__ __align__(256) bf16 g_wih[(size_t)HD * HE];
__device__ __align__(256) bf16 g_wil[(size_t)HD * HE];
// activations (h double-buffered)
__device__ __align__(256) bf16 g_hh0[(size_t)BATCH * HD];
__device__ __align__(256) bf16 g_hl0[(size_t)BATCH * HD];
__device__ __align__(256) bf16 g_hh1[(size_t)BATCH * HD];
__device__ __align__(256) bf16 g_hl1[(size_t)BATCH * HD];
__device__ __align__(256) float g_c[(size_t)BATCH * HD];
__device__ __align__(256) float g_q[(size_t)BATCH * HD];
__device__ __align__(256) float g_ahpre[(size_t)BATCH * HD];
__device__ __align__(256) bf16 g_ahh_all[(size_t)TT * BATCH * HD];
__device__ __align__(256) bf16 g_ahl_all[(size_t)TT * BATCH * HD];
__device__ __align__(256) float g_logits_all[(size_t)TT * BATCH * 121];
__device__ __align__(256) float g_ctxdot[(size_t)TT * BATCH];

// ---------------- math helpers (fast MUFU paths only) ----------------
__device__ __forceinline__ float tanh_fast(float x) {
    float e = __expf(2.0f * x);
    return 1.0f - __fdividef(2.0f, e + 1.0f);
}
__device__ __forceinline__ float sigmoid_fast(float x) {
    return __fdividef(1.0f, 1.0f + __expf(-x));
}
__device__ __forceinline__ void split2(float v, bf16* hi, bf16* lo) {
    bf16 h = __float2bfloat16(v);
    *hi = h;
    *lo = __float2bfloat16(v - __bfloat162float(h));
}

// ---------------- PTX helpers ----------------
__device__ __forceinline__ u32 smem_u32(const void* p) {
    u32 a;
    asm("{ .reg .u64 t; cvta.to.shared.u64 t, %1; cvt.u32.u64 %0, t; }"
        : "=r"(a) : "l"(p));
    return a;
}
__device__ __forceinline__ void cp16(u32 d, const void* s, u32 sz) {
    asm volatile("cp.async.cg.shared.global [%0], [%1], 16, %2;"
                 :: "r"(d), "l"(s), "r"(sz) : "memory");
}
__device__ __forceinline__ void cp_commit() {
    asm volatile("cp.async.commit_group;" ::: "memory");
}
template<int N>
__device__ __forceinline__ void cp_wait() {
    asm volatile("cp.async.wait_group %0;" :: "n"(N) : "memory");
}
__device__ __forceinline__ void ldsm_x4(u32* r, u32 a) {
    asm volatile("ldmatrix.sync.aligned.m8n8.x4.shared.b16 {%0,%1,%2,%3}, [%4];"
                 : "=r"(r[0]), "=r"(r[1]), "=r"(r[2]), "=r"(r[3]) : "r"(a));
}
__device__ __forceinline__ void mma_bf16(float* c, const u32* a, const u32* b) {
    asm volatile(
        "mma.sync.aligned.m16n8k16.row.col.f32.bf16.bf16.f32 "
        "{%0,%1,%2,%3}, {%4,%5,%6,%7}, {%8,%9}, {%0,%1,%2,%3};"
        : "+f"(c[0]), "+f"(c[1]), "+f"(c[2]), "+f"(c[3])
        : "r"(a[0]), "r"(a[1]), "r"(a[2]), "r"(a[3]), "r"(b[0]), "r"(b[1]));
}

// ======== shared mainloop macro pieces (BN=128 and BN=64 kernels) ========
// per-buffer layout: Ah@0 Al@10240 Bh@20480 Bl@20480+BN*80; row stride 80 B.

#define GEMM_MAINLOOP(BN, NTN, LDA, LDB, NREAL, BNOFF)                          \
    constexpr int BUFB = 20480 + (BN) * 160;                                    \
    constexpr int BLO  = (BN) * 80;                                             \
    extern __shared__ char smem[];                                              \
    const u32 sb = smem_u32(smem);                                              \
    const int tid = threadIdx.x, lane = tid & 31, wid = tid >> 5;               \
    const int bm = blockIdx.y * 128, bn = (blockIdx.x + (BNOFF)) * (BN);        \
    const int wm = (wid >> 1) * 32, wn = (wid & 1) * ((BN) / 2);                \
    float acc[2][NTN][4];                                                       \
    _Pragma("unroll") for (int m = 0; m < 2; m++)                               \
    _Pragma("unroll") for (int n = 0; n < NTN; n++)                             \
    _Pragma("unroll") for (int j = 0; j < 4; j++) acc[m][n][j] = 0.0f;          \
    const int nch = K / 32;                                                     \
    auto stage = [&](int c) {                                                   \
        const int kt = c * 32;                                                  \
        const u32 bufb = sb + (u32)(c & 1) * BUFB;                              \
        _Pragma("unroll") for (int p = 0; p < 2; p++) {                         \
            int v = tid + p * 256, row = v >> 2, g = v & 3;                     \
            size_t go = (size_t)(bm + row) * (LDA) + kt + g * 8;                \
            u32 sa = bufb + row * 80 + g * 16;                                  \
            cp16(sa, Ah_ + go, 16);                                             \
            cp16(sa + 10240, Al_ + go, 16);                                     \
        }                                                                       \
        _Pragma("unroll") for (int p = 0; p < (BN) / 64; p++) {                 \
            int v = tid + p * 256, row = v >> 2, g = v & 3;                     \
            int n = bn + row;                                                   \
            int na = (n < (NREAL)) ? n : ((NREAL) - 1);                         \
            u32 sz = (n < (NREAL)) ? 16u : 0u;                                  \
            size_t go = (size_t)na * (LDB) + kt + g * 8;                        \
            u32 sa = bufb + 20480 + row * 80 + g * 16;                          \
            cp16(sa, Bh + go, sz);                                              \
            cp16(sa + BLO, Bl + go, sz);                                        \
        }                                                                       \
    };                                                                          \
    stage(0);                                                                   \
    cp_commit();                                                                \
    for (int c = 0; c < nch; c++) {                                             \
        if (c + 1 < nch) { stage(c + 1); cp_commit(); cp_wait<1>(); }           \
        else             { cp_wait<0>(); }                                      \
        __syncthreads();                                                        \
        const u32 bufb = sb + (u32)(c & 1) * BUFB;                              \
        _Pragma("unroll") for (int k2 = 0; k2 < 2; k2++) {                      \
            const u32 kb = k2 * 32;                                             \
            const u32 a0 = bufb + (wm + (lane & 15)) * 80 + kb + (lane >> 4) * 16; \
            const u32 a1 = a0 + 16 * 80;                                        \
            u32 ahf[2][4], alf[2][4];                                           \
            ldsm_x4(ahf[0], a0); ldsm_x4(ahf[1], a1);                           \
            ldsm_x4(alf[0], a0 + 10240); ldsm_x4(alf[1], a1 + 10240);           \
            const u32 bb0 = bufb + 20480 +                                      \
                (wn + (lane & 7) + ((lane >> 4) & 1) * 8) * 80 +                \
                kb + ((lane >> 3) & 1) * 16;                                    \
            _Pragma("unroll") for (int nt2 = 0; nt2 < (NTN) / 2; nt2++) {       \
                u32 ba = bb0 + nt2 * 16 * 80;                                   \
                u32 bh4[4], bl4[4];                                             \
                ldsm_x4(bh4, ba); ldsm_x4(bl4, ba + BLO);                       \
                _Pragma("unroll") for (int half = 0; half < 2; half++) {        \
                    int nt = nt2 * 2 + half;                                    \
                    const u32* bhf = bh4 + half * 2;                            \
                    const u32* blf = bl4 + half * 2;                            \
                    _Pragma("unroll") for (int m = 0; m < 2; m++) {             \
                        mma_bf16(acc[m][nt], ahf[m], bhf);                      \
                        mma_bf16(acc[m][nt], ahf[m], blf);                      \
                        mma_bf16(acc[m][nt], alf[m], bhf);                      \
                    }                                                           \
                }                                                               \
            }                                                                   \
        }                                                                       \
        __syncthreads();                                                        \
    }

// ---------------- generic GEMM (prep / ah / logits) ----------------
template<int BN, bool DOTANH, bool SPLITOUT>
__global__ __launch_bounds__(256, 2)
void mma_gemm_k(const bf16* __restrict__ Ah_, const bf16* __restrict__ Al_,
                int lda,
                const bf16* __restrict__ Bh, const bf16* __restrict__ Bl, int ldb,
                const float* __restrict__ bias,
                const float* __restrict__ Cadd,
                float* __restrict__ C, bf16* __restrict__ Ch, bf16* __restrict__ Cl,
                int K, int Nreal)
{
    GEMM_MAINLOOP(BN, BN / 16, lda, ldb, Nreal, 0)

    auto emit = [&](int r, int n, float v) {
        if (n >= Nreal) return;
        size_t o = (size_t)r * Nreal + n;
        if (bias) v += bias[n];
        if (Cadd) v += Cadd[o];
        if (DOTANH) v = tanh_fast(v);
        if (C) C[o] = v;
        if (SPLITOUT) split2(v, &Ch[o], &Cl[o]);
    };
#pragma unroll
    for (int m = 0; m < 2; m++) {
        int r0 = bm + wm + m * 16 + (lane >> 2);
#pragma unroll
        for (int nt = 0; nt < BN / 16; nt++) {
            int gn = bn + wn + nt * 8 + (lane & 3) * 2;
            emit(r0,     gn,     acc[m][nt][0]);
            emit(r0,     gn + 1, acc[m][nt][1]);
            emit(r0 + 8, gn,     acc[m][nt][2]);
            emit(r0 + 8, gn + 1, acc[m][nt][3]);
        }
    }
}

// ---------------- fused recurrent GEMM + LSTM cell ----------------
// Cols [0,2048): interleaved gates (4d+g, g order i,f,g,o). Epilogue applies
// the cell with emb_proj[token] and writes split h. Cols [2048,2560): q.
__global__ __launch_bounds__(256, 2)
void comb_cell_k(const bf16* __restrict__ Ah_, const bf16* __restrict__ Al_,
                 const bf16* __restrict__ Bh, const bf16* __restrict__ Bl,
                 const float* __restrict__ ep,     // [VOC][2048]
                 const int* __restrict__ tgt,
                 const float* __restrict__ bq,     // bcomb (q bias region)
                 float* __restrict__ cst,
                 bf16* __restrict__ houth, bf16* __restrict__ houtl,
                 float* __restrict__ qout,
                 int tok_step, int noff)
{
    const int K = HD;
    GEMM_MAINLOOP(128, 8, HD, HD, NCOMB, noff)

    if (bn < 4 * HD) {
        // gate region: apply LSTM cell
#pragma unroll
        for (int m = 0; m < 2; m++) {
            int r0 = bm + wm + m * 16 + (lane >> 2);
            int r1 = r0 + 8;
            int tok0 = (tok_step == 0) ? START_TOKEN : tgt[(size_t)r0 * TT + tok_step - 1];
            int tok1 = (tok_step == 0) ? START_TOKEN : tgt[(size_t)r1 * TT + tok_step - 1];
            const float* e0 = ep + (size_t)tok0 * 4 * HD;
            const float* e1 = ep + (size_t)tok1 * 4 * HD;
#pragma unroll
            for (int nt = 0; nt < 8; nt++) {
                int gn = bn + wn + nt * 8 + (lane & 3) * 2;
                float v0 = acc[m][nt][0] + e0[gn];
                float v1 = acc[m][nt][1] + e0[gn + 1];
                float v2 = acc[m][nt][2] + e1[gn];
                float v3 = acc[m][nt][3] + e1[gn + 1];
                float p0 = __shfl_xor_sync(0xffffffffu, v0, 1);
                float p1 = __shfl_xor_sync(0xffffffffu, v1, 1);
                float p2 = __shfl_xor_sync(0xffffffffu, v2, 1);
                float p3 = __shfl_xor_sync(0xffffffffu, v3, 1);
                if (!(lane & 1)) {
                    int d = gn >> 2;
                    // row r0: i=v0 f=v1 g=p0 o=p1
                    {
                        size_t ci = (size_t)r0 * HD + d;
                        float cn = sigmoid_fast(v1) * cst[ci]
                                 + sigmoid_fast(v0) * tanh_fast(p0);
                        cst[ci] = cn;
                        float hn = sigmoid_fast(p1) * tanh_fast(cn);
                        split2(hn, &houth[ci], &houtl[ci]);
                    }
                    {
                        size_t ci = (size_t)r1 * HD + d;
                        float cn = sigmoid_fast(v3) * cst[ci]
                                 + sigmoid_fast(v2) * tanh_fast(p2);
                        cst[ci] = cn;
                        float hn = sigmoid_fast(p3) * tanh_fast(cn);
                        split2(hn, &houth[ci], &houtl[ci]);
                    }
                }
            }
        }
    } else {
        // q region
#pragma unroll
        for (int m = 0; m < 2; m++) {
            int r0 = bm + wm + m * 16 + (lane >> 2);
#pragma unroll
            for (int nt = 0; nt < 8; nt++) {
                int gn = bn + wn + nt * 8 + (lane & 3) * 2;
                int qn = gn - 4 * HD;
                float b0 = bq[gn], b1 = bq[gn + 1];
                qout[(size_t)r0 * HD + qn]           = acc[m][nt][0] + b0;
                qout[(size_t)r0 * HD + qn + 1]       = acc[m][nt][1] + b1;
                qout[(size_t)(r0 + 8) * HD + qn]     = acc[m][nt][2] + b0;
                qout[(size_t)(r0 + 8) * HD + qn + 1] = acc[m][nt][3] + b1;
            }
        }
    }
}

// ---------------- prep kernels ----------------
__global__ void split_arr_k(const float* __restrict__ src,
                            bf16* __restrict__ h, bf16* __restrict__ l, size_t n)
{
    for (size_t i = (size_t)blockIdx.x * blockDim.x + threadIdx.x; i < n;
         i += (size_t)gridDim.x * blockDim.x)
        split2(src[i], &h[i], &l[i]);
}

__global__ void transpose_split_k(const float* __restrict__ src,  // [K][N]
                                  bf16* __restrict__ h, bf16* __restrict__ l,
                                  int Kd, int Nd)
{
    size_t n = (size_t)Kd * Nd;
    for (size_t i = (size_t)blockIdx.x * blockDim.x + threadIdx.x; i < n;
         i += (size_t)gridDim.x * blockDim.x) {
        int k = (int)(i / Nd), nn = (int)(i % Nd);
        split2(src[i], &h[(size_t)nn * Kd + k], &l[(size_t)nn * Kd + k]);
    }
}

// comb weight rows: n<2048: interleaved gates — source W_hh row (n&3)*512+(n>>2)
//                   n>=2048: W_dec^T
__global__ void prep_comb_k(const float* __restrict__ W_hh,
                            const float* __restrict__ W_dec,
                            const float* __restrict__ b_attn,
                            bf16* __restrict__ wh, bf16* __restrict__ wl,
                            float* __restrict__ bc)
{
    size_t n = (size_t)NCOMB * HD;
    for (size_t i = (size_t)blockIdx.x * blockDim.x + threadIdx.x; i < n;
         i += (size_t)gridDim.x * blockDim.x) {
        int row = (int)(i / HD), k = (int)(i % HD);
        float v;
        if (row < 4 * HD) {
            int src = (row & 3) * HD + (row >> 2);
            v = W_hh[(size_t)src * HD + k];
        } else {
            v = W_dec[(size_t)k * HD + (row - 4 * HD)];
        }
        split2(v, &wh[i], &wl[i]);
        if (i < NCOMB) bc[i] = (i < 4 * HD) ? 0.0f : b_attn[i - 4 * HD];
    }
}

// ep[tok][n], n=4d+g: source W_ih row (n&3)*512+(n>>2), + b_ih + b_hh
__global__ void embproj_k(const float* __restrict__ embed,
                          const float* __restrict__ W_ih,
                          const float* __restrict__ b_ih,
                          const float* __restrict__ b_hh,
                          float* __restrict__ ep)
{
    int v = blockIdx.y;
    int n = blockIdx.x * 128 + threadIdx.x;
    int j = (n & 3) * HD + (n >> 2);
    __shared__ float em[EMB];
    if (threadIdx.x < EMB) em[threadIdx.x] = embed[(size_t)v * EMB + threadIdx.x];
    __syncthreads();
    float acc = b_ih[j] + b_hh[j];
    const float* w = W_ih + (size_t)j * EMB;
#pragma unroll 8
    for (int k = 0; k < EMB; k++) acc += em[k] * w[k];
    ep[(size_t)v * 4 * HD + n] = acc;
}

__global__ void prep_outw_k(const float* __restrict__ W_out,
                            const float* __restrict__ b_out,
                            const float* __restrict__ w_copy,
                            const float* __restrict__ b_copy,
                            bf16* __restrict__ wh, bf16* __restrict__ wl,
                            float* __restrict__ bo)
{
    size_t n = (size_t)121 * HD;
    for (size_t i = (size_t)blockIdx.x * blockDim.x + threadIdx.x; i < n;
         i += (size_t)gridDim.x * blockDim.x) {
        int row = (int)(i / HD), k = (int)(i % HD);
        float v = (row < VOC) ? W_out[(size_t)row * HD + k] : w_copy[k];
        split2(v, &wh[i], &wl[i]);
        if (i < 121) bo[i] = (i < VOC) ? b_out[i] : b_copy[0];
    }
}

__global__ void encw_k(const float* __restrict__ enc,
                       const float* __restrict__ w_copy,
                       float* __restrict__ encw)
{
    int r = blockIdx.x;
    int tid = threadIdx.x;
    __shared__ float red[128];
    const float* row = enc + (size_t)r * HE;
    float acc = 0.f;
    for (int k = tid; k < HE; k += 128) acc += row[k] * w_copy[HD + k];
    red[tid] = acc;
    __syncthreads();
    for (int s2 = 64; s2; s2 >>= 1) {
        if (tid < s2) red[tid] += red[tid + s2];
        __syncthreads();
    }
    if (tid == 0) encw[r] = red[0];
}

__global__ void zero_c_k(float* __restrict__ c)
{
    size_t i = (size_t)blockIdx.x * blockDim.x + threadIdx.x;
    if (i < (size_t)BATCH * HD) c[i] = 0.0f;
}

// ---------------- attention (vectorized) ----------------
__global__ void attn_k(const float* __restrict__ encproj,
                       const float* __restrict__ ctxw,
                       const float* __restrict__ encw,
                       const float* __restrict__ q,     // dense [B][HD]
                       const float* __restrict__ v_attn,
                       float* __restrict__ attn_out,
                       float* __restrict__ ahpre,
                       float* __restrict__ ctxdot,
                       int t)
{
    int b = blockIdx.x;
    int tid = threadIdx.x;
    __shared__ __align__(16) float qsh[HD];
    __shared__ __align__(16) float vsh[HD];
    __shared__ float sc[SEQ];
    __shared__ float aprob[SEQ];

    for (int d = tid; d < HD; d += 128) {
        qsh[d] = q[(size_t)b * HD + d];
        vsh[d] = v_attn[d];
    }
    __syncthreads();

    int w = tid >> 5, lane = tid & 31;
    const float* ep = encproj + (size_t)b * SEQ * HD;
    for (int s = w; s < SEQ; s += 4) {
        float acc = 0.f;
        const float4* row4 = (const float4*)(ep + (size_t)s * HD);
#pragma unroll
        for (int j = 0; j < 4; j++) {
            int d4 = lane + j * 32;          // float4 index
            float4 e4 = row4[d4];
            float4 q4 = *(const float4*)&qsh[d4 * 4];
            float4 v4 = *(const float4*)&vsh[d4 * 4];
            acc += tanh_fast(e4.x + q4.x) * v4.x;
            acc += tanh_fast(e4.y + q4.y) * v4.y;
            acc += tanh_fast(e4.z + q4.z) * v4.z;
            acc += tanh_fast(e4.w + q4.w) * v4.w;
        }
#pragma unroll
        for (int o = 16; o; o >>= 1) acc += __shfl_xor_sync(0xffffffffu, acc, o);
        if (lane == 0) sc[s] = acc;
    }
    __syncthreads();

    if (tid < 32) {
        // scores are O(1): softmax without max-subtraction is exact enough
        float e = (tid < SEQ) ? __expf(sc[tid]) : 0.f;
        float sum = e;
#pragma unroll
        for (int o = 16; o; o >>= 1) sum += __shfl_xor_sync(0xffffffffu, sum, o);
        float a = __fdividef(e, sum);
        float cd = 0.f;
        if (tid < SEQ) {
            aprob[tid] = a;
            attn_out[(size_t)b * TT * SEQ + (size_t)t * SEQ + tid] = a;
            cd = a * encw[(size_t)b * SEQ + tid];
        }
#pragma unroll
        for (int o = 16; o; o >>= 1) cd += __shfl_xor_sync(0xffffffffu, cd, o);
        if (tid == 0) ctxdot[(size_t)t * BATCH + b] = cd;
    }
    __syncthreads();

    // ahpre[b][d] = sum_s aprob[s] * ctxw[b,s,d]  (float4, one pass)
    {
        const float4* cw4 = (const float4*)(ctxw + (size_t)b * SEQ * HD);
        float4 acc4 = make_float4(0.f, 0.f, 0.f, 0.f);
#pragma unroll
        for (int s = 0; s < SEQ; s++) {
            float a = aprob[s];
            float4 v = cw4[s * (HD / 4) + tid];
            acc4.x += a * v.x; acc4.y += a * v.y;
            acc4.z += a * v.z; acc4.w += a * v.w;
        }
        ((float4*)(ahpre + (size_t)b * HD))[tid] = acc4;
    }
}

// ---------------- output mix: warp per (t,b) row ----------------
__global__ void out2_k(const float* __restrict__ logits_all,  // [T*B][121]
                       const float* __restrict__ ctxdot,
                       const int* __restrict__ input_char_ids,
                       const float* __restrict__ attn_base,
                       float* __restrict__ outputs)
{
    int warp = threadIdx.x >> 5, lane = threadIdx.x & 31;
    int row = blockIdx.x * 4 + warp;
    int t = row >> 12;
    int b = row & 4095;
    __shared__ float cbuf[4][VOC];

    for (int k = lane; k < VOC; k += 32) cbuf[warp][k] = 0.f;
    __syncwarp();
    if (lane < SEQ) {
        int id = input_char_ids[(size_t)b * SEQ + lane];
        float a = attn_base[(size_t)b * TT * SEQ + (size_t)t * SEQ + lane];
        atomicAdd(&cbuf[warp][id], a);
    }
    __syncwarp();

    const float* lrow = logits_all + (size_t)row * 121;
    float p = sigmoid_fast(lrow[120] + ctxdot[row]);

    float e[4];
    float sum = 0.f;
#pragma unroll
    for (int j = 0; j < 4; j++) {
        int idx = lane + j * 32;
        e[j] = (idx < VOC) ? __expf(lrow[idx]) : 0.f;
        sum += e[j];
    }
#pragma unroll
    for (int o = 16; o; o >>= 1) sum += __shfl_xor_sync(0xffffffffu, sum, o);
    float inv = __fdividef(1.0f - p, sum);
#pragma unroll
    for (int j = 0; j < 4; j++) {
        int idx = lane + j * 32;
        if (idx < VOC)
            outputs[(size_t)b * TT * VOC + (size_t)t * VOC + idx] =
                inv * e[j] + p * cbuf[warp][idx];
    }
}

// ---------------- host ----------------
#define SYM(p, s) cudaGetSymbolAddress((void**)&(p), s)
#define SM128 81920
#define SM64  61440

extern "C" void kernel_launch(void* const* d_in, const int* in_sizes, int n_in,
                              void* d_out, int out_size)
{
    (void)in_sizes; (void)n_in; (void)out_size;
    const float* enc        = (const float*)d_in[0];
    const float* enc_final  = (const float*)d_in[1];
    const int*   tgt        = (const int*)d_in[2];
    const int*   input_ids  = (const int*)d_in[3];
    const float* embed      = (const float*)d_in[4];
    const float* W_init     = (const float*)d_in[5];
    const float* b_init     = (const float*)d_in[6];
    const float* W_ih       = (const float*)d_in[7];
    const float* W_hh       = (const float*)d_in[8];
    const float* b_ih       = (const float*)d_in[9];
    const float* b_hh       = (const float*)d_in[10];
    const float* W_enc_attn = (const float*)d_in[11];
    const float* W_dec_attn = (const float*)d_in[12];
    const float* b_attn     = (const float*)d_in[13];
    const float* v_attn     = (const float*)d_in[14];
    const float* W_ap       = (const float*)d_in[15];
    const float* b_ap       = (const float*)d_in[16];
    const float* W_out      = (const float*)d_in[17];
    const float* b_out      = (const float*)d_in[18];
    const float* w_copy     = (const float*)d_in[19];
    const float* b_copy     = (const float*)d_in[20];

    float* out = (float*)d_out;
    float* outputs   = out;
    float* attn_base = out + (size_t)BATCH * TT * VOC;

    bf16 *ench, *encl, *efh, *efl;
    bf16 *wcombh, *wcombl, *weh, *wel, *waph, *wapl, *woch, *wocl, *wih, *wil;
    bf16 *hh0, *hl0, *hh1, *hl1, *ahh, *ahl;
    float *encproj, *ctxwp, *encw, *embproj, *bcomb, *boc, *cst;
    float *q, *ahpre, *logits_all, *ctxdot;
    SYM(ench, g_ench); SYM(encl, g_encl);
    SYM(efh, g_efh);   SYM(efl, g_efl);
    SYM(encproj, g_encproj); SYM(ctxwp, g_ctxw); SYM(encw, g_encw);
    SYM(embproj, g_embproj);
    SYM(wcombh, g_wcombh); SYM(wcombl, g_wcombl); SYM(bcomb, g_bcomb);
    SYM(weh, g_weh);   SYM(wel, g_wel);
    SYM(waph, g_waph); SYM(wapl, g_wapl);
    SYM(woch, g_woch); SYM(wocl, g_wocl); SYM(boc, g_boc);
    SYM(wih, g_wih);   SYM(wil, g_wil);
    SYM(hh0, g_hh0);   SYM(hl0, g_hl0);
    SYM(hh1, g_hh1);   SYM(hl1, g_hl1);
    SYM(cst, g_c);     SYM(q, g_q); SYM(ahpre, g_ahpre);
    SYM(ahh, g_ahh_all); SYM(ahl, g_ahl_all);
    SYM(logits_all, g_logits_all); SYM(ctxdot, g_ctxdot);

    bf16* hbh[2] = {hh0, hh1};
    bf16* hbl[2] = {hl0, hl1};

    cudaFuncSetAttribute(mma_gemm_k<128, false, false>,
                         cudaFuncAttributeMaxDynamicSharedMemorySize, SM128);
    cudaFuncSetAttribute(mma_gemm_k<64, false, true>,
                         cudaFuncAttributeMaxDynamicSharedMemorySize, SM64);
    cudaFuncSetAttribute(mma_gemm_k<64, true, true>,
                         cudaFuncAttributeMaxDynamicSharedMemorySize, SM64);
    cudaFuncSetAttribute(comb_cell_k,
                         cudaFuncAttributeMaxDynamicSharedMemorySize, SM128);

    // ---- prep ----
    split_arr_k<<<4096, 256>>>(enc, ench, encl, (size_t)BATCH * SEQ * HE);
    split_arr_k<<<2048, 256>>>(enc_final, efh, efl, (size_t)BATCH * HE);
    embproj_k<<<dim3(16, VOC), 128>>>(embed, W_ih, b_ih, b_hh, embproj);
    prep_comb_k<<<2048, 256>>>(W_hh, W_dec_attn, b_attn, wcombh, wcombl, bcomb);
    transpose_split_k<<<1024, 256>>>(W_enc_attn, weh, wel, HE, HD);
    split_arr_k<<<1024, 256>>>(W_ap, waph, wapl, (size_t)HD * (HD + HE));
    prep_outw_k<<<256, 256>>>(W_out, b_out, w_copy, b_copy, woch, wocl, boc);
    split_arr_k<<<1024, 256>>>(W_init, wih, wil, (size_t)HD * HE);
    encw_k<<<BATCH * SEQ, 128>>>(enc, w_copy, encw);
    zero_c_k<<<(BATCH * HD + 255) / 256, 256>>>(cst);

    // h^{-1} = enc_final @ W_init^T + b_init  -> hbuf0
    mma_gemm_k<64, false, true><<<dim3(8, 32), 256, SM64>>>(
        efh, efl, HE, wih, wil, HE, b_init, nullptr,
        nullptr, hh0, hl0, HE, HD);
    // enc_proj, ctxw
    mma_gemm_k<128, false, false><<<dim3(4, 768), 256, SM128>>>(
        ench, encl, HE, weh, wel, HE, nullptr, nullptr,
        encproj, nullptr, nullptr, HE, HD);
    mma_gemm_k<128, false, false><<<dim3(4, 768), 256, SM128>>>(
        ench, encl, HE, waph + HD, wapl + HD, HD + HE, nullptr, nullptr,
        ctxwp, nullptr, nullptr, HE, HD);

    // prologue: gates^0 from h^{-1}, cell token 0 -> h^0 in hbuf1
    comb_cell_k<<<dim3(16, 32), 256, SM128>>>(
        hh0, hl0, wcombh, wcombl, embproj, tgt, bcomb,
        cst, hh1, hl1, q, /*tok_step=*/0, /*noff=*/0);

    for (int t = 0; t < TT; t++) {
        int cur = (t + 1) & 1;   // h^t lives here
        int nxt = t & 1;
        if (t < TT - 1) {
            // q^t from h^t; gates^{t+1} + cell(token t+1) -> h^{t+1}
            comb_cell_k<<<dim3(20, 32), 256, SM128>>>(
                hbh[cur], hbl[cur], wcombh, wcombl, embproj, tgt, bcomb,
                cst, hbh[nxt], hbl[nxt], q, t + 1, 0);
        } else {
            // last step: q only
            comb_cell_k<<<dim3(4, 32), 256, SM128>>>(
                hbh[cur], hbl[cur], wcombh, wcombl, embproj, tgt, bcomb,
                cst, nullptr, nullptr, q, 0, 16);
        }
        attn_k<<<BATCH, 128>>>(encproj, ctxwp, encw, q, v_attn,
                               attn_base, ahpre, ctxdot, t);
        // ah = tanh(h^t @ W_ap[:, :512]^T + ahpre + b_ap)
        mma_gemm_k<64, true, true><<<dim3(8, 32), 256, SM64>>>(
            hbh[cur], hbl[cur], HD, waph, wapl, HD + HE, b_ap, ahpre,
            nullptr,
            ahh + (size_t)t * BATCH * HD, ahl + (size_t)t * BATCH * HD,
            HD, HD);
    }

    // deferred logits+copy GEMM: M = T*B, N = 121, K = 512
    mma_gemm_k<128, false, false><<<dim3(1, (TT * BATCH) / 128), 256, SM128>>>(
        ahh, ahl, HD, woch, wocl, HD, boc, nullptr,
        logits_all, nullptr, nullptr, HD, 121);
    out2_k<<<TT * BATCH / 4, 128>>>(logits_all, ctxdot, input_ids, attn_base, outputs);
}

// round 7
// speedup vs baseline: 1.8612x; 1.2486x over previous
#include <cuda_runtime.h>
#include <cuda_fp16.h>
#include <cstdint>

#define BATCH 4096
#define SEQ   24
#define TT    32
#define VOC   120
#define EMB   128
#define HE    512
#define HD    512
#define START_TOKEN 2
#define NCOMB 3072   // 2048 interleaved gates + 512 q + 512 ahp2

typedef __half fp16;
typedef unsigned int u32;

// ---------------- device scratch ----------------
__device__ __align__(256) fp16 g_ench[(size_t)BATCH * SEQ * HE];
__device__ __align__(256) fp16 g_encl[(size_t)BATCH * SEQ * HE];
__device__ __align__(256) fp16 g_efh[(size_t)BATCH * HE];
__device__ __align__(256) fp16 g_efl[(size_t)BATCH * HE];
__device__ __align__(256) float g_encproj[(size_t)BATCH * SEQ * HD];
__device__ __align__(256) float g_ctxw[(size_t)BATCH * SEQ * HD];
__device__ __align__(256) float g_encw[(size_t)BATCH * SEQ];
__device__ __align__(256) float g_embproj[(size_t)VOC * 4 * HD];   // [tok][4d+g]
// weights (single fp16)
__device__ __align__(256) fp16 g_wcomb[(size_t)NCOMB * HD];
__device__ __align__(256) float g_bcomb[NCOMB];
__device__ __align__(256) fp16 g_we[(size_t)HE * HD];
__device__ __align__(256) fp16 g_wapc[(size_t)HD * HE];    // W_ap[:,512:] rows
__device__ __align__(256) fp16 g_woc[(size_t)121 * HD];
__device__ __align__(256) float g_boc[121];
__device__ __align__(256) fp16 g_wi[(size_t)HD * HE];
// activations (h double-buffered, fp16 hi/lo)
__device__ __align__(256) fp16 g_hh0[(size_t)BATCH * HD];
__device__ __align__(256) fp16 g_hl0[(size_t)BATCH * HD];
__device__ __align__(256) fp16 g_hh1[(size_t)BATCH * HD];
__device__ __align__(256) fp16 g_hl1[(size_t)BATCH * HD];
__device__ __align__(256) float g_c[(size_t)BATCH * HD];
__device__ __align__(256) float g_q[(size_t)BATCH * HD];
__device__ __align__(256) float g_ahp2[(size_t)BATCH * HD];
__device__ __align__(256) fp16 g_ahh_all[(size_t)TT * BATCH * HD];
__device__ __align__(256) fp16 g_ahl_all[(size_t)TT * BATCH * HD];
__device__ __align__(256) float g_logits_all[(size_t)TT * BATCH * 121];
__device__ __align__(256) float g_ctxdot[(size_t)TT * BATCH];

// ---------------- math helpers ----------------
__device__ __forceinline__ float tanh_fast(float x) {
    float e = __expf(2.0f * x);
    return 1.0f - __fdividef(2.0f, e + 1.0f);
}
__device__ __forceinline__ float sigmoid_fast(float x) {
    return __fdividef(1.0f, 1.0f + __expf(-x));
}
__device__ __forceinline__ void split2h(float v, fp16* hi, fp16* lo) {
    fp16 h = __float2half(v);
    *hi = h;
    *lo = __float2half(v - __half2float(h));
}

// ---------------- PTX helpers ----------------
__device__ __forceinline__ u32 smem_u32(const void* p) {
    u32 a;
    asm("{ .reg .u64 t; cvta.to.shared.u64 t, %1; cvt.u32.u64 %0, t; }"
        : "=r"(a) : "l"(p));
    return a;
}
__device__ __forceinline__ void cp16(u32 d, const void* s, u32 sz) {
    asm volatile("cp.async.cg.shared.global [%0], [%1], 16, %2;"
                 :: "r"(d), "l"(s), "r"(sz) : "memory");
}
__device__ __forceinline__ void cp_commit() {
    asm volatile("cp.async.commit_group;" ::: "memory");
}
template<int N>
__device__ __forceinline__ void cp_wait() {
    asm volatile("cp.async.wait_group %0;" :: "n"(N) : "memory");
}
__device__ __forceinline__ void ldsm_x4(u32* r, u32 a) {
    asm volatile("ldmatrix.sync.aligned.m8n8.x4.shared.b16 {%0,%1,%2,%3}, [%4];"
                 : "=r"(r[0]), "=r"(r[1]), "=r"(r[2]), "=r"(r[3]) : "r"(a));
}
__device__ __forceinline__ void mma_f16(float* c, const u32* a, const u32* b) {
    asm volatile(
        "mma.sync.aligned.m16n8k16.row.col.f32.f16.f16.f32 "
        "{%0,%1,%2,%3}, {%4,%5,%6,%7}, {%8,%9}, {%0,%1,%2,%3};"
        : "+f"(c[0]), "+f"(c[1]), "+f"(c[2]), "+f"(c[3])
        : "r"(a[0]), "r"(a[1]), "r"(a[2]), "r"(a[3]), "r"(b[0]), "r"(b[1]));
}

// ======== GEMM mainloop: A fp16 hi/lo pair, B single fp16 ========
// per-buffer: Ah@0 Al@10240 B@20480 (BN*80 bytes); row stride 80 B.

#define GEMM_MAINLOOP(BN, NTN, LDA, LDB, NREAL, BNOFF)                          \
    constexpr int BUFB = 20480 + (BN) * 80;                                     \
    extern __shared__ char smem[];                                              \
    const u32 sb = smem_u32(smem);                                              \
    const int tid = threadIdx.x, lane = tid & 31, wid = tid >> 5;               \
    const int bm = blockIdx.y * 128, bn = (blockIdx.x + (BNOFF)) * (BN);        \
    const int wm = (wid >> 1) * 32, wn = (wid & 1) * ((BN) / 2);                \
    float acc[2][NTN][4];                                                       \
    _Pragma("unroll") for (int m = 0; m < 2; m++)                               \
    _Pragma("unroll") for (int n = 0; n < NTN; n++)                             \
    _Pragma("unroll") for (int j = 0; j < 4; j++) acc[m][n][j] = 0.0f;          \
    const int nch = K / 32;                                                     \
    auto stage = [&](int c) {                                                   \
        const int kt = c * 32;                                                  \
        const u32 bufb = sb + (u32)(c & 1) * BUFB;                              \
        _Pragma("unroll") for (int p = 0; p < 2; p++) {                         \
            int v = tid + p * 256, row = v >> 2, g = v & 3;                     \
            size_t go = (size_t)(bm + row) * (LDA) + kt + g * 8;                \
            u32 sa = bufb + row * 80 + g * 16;                                  \
            cp16(sa, Ah_ + go, 16);                                             \
            cp16(sa + 10240, Al_ + go, 16);                                     \
        }                                                                       \
        _Pragma("unroll") for (int p = 0; p < (BN) / 64; p++) {                 \
            int v = tid + p * 256, row = v >> 2, g = v & 3;                     \
            int n = bn + row;                                                   \
            int na = (n < (NREAL)) ? n : ((NREAL) - 1);                         \
            u32 sz = (n < (NREAL)) ? 16u : 0u;                                  \
            size_t go = (size_t)na * (LDB) + kt + g * 8;                        \
            u32 sa = bufb + 20480 + row * 80 + g * 16;                          \
            cp16(sa, Bw + go, sz);                                              \
        }                                                                       \
    };                                                                          \
    stage(0);                                                                   \
    cp_commit();                                                                \
    for (int c = 0; c < nch; c++) {                                             \
        if (c + 1 < nch) { stage(c + 1); cp_commit(); cp_wait<1>(); }           \
        else             { cp_wait<0>(); }                                      \
        __syncthreads();                                                        \
        const u32 bufb = sb + (u32)(c & 1) * BUFB;                              \
        _Pragma("unroll") for (int k2 = 0; k2 < 2; k2++) {                      \
            const u32 kb = k2 * 32;                                             \
            const u32 a0 = bufb + (wm + (lane & 15)) * 80 + kb + (lane >> 4) * 16; \
            const u32 a1 = a0 + 16 * 80;                                        \
            u32 ahf[2][4], alf[2][4];                                           \
            ldsm_x4(ahf[0], a0); ldsm_x4(ahf[1], a1);                           \
            ldsm_x4(alf[0], a0 + 10240); ldsm_x4(alf[1], a1 + 10240);           \
            const u32 bb0 = bufb + 20480 +                                      \
                (wn + (lane & 7) + ((lane >> 4) & 1) * 8) * 80 +                \
                kb + ((lane >> 3) & 1) * 16;                                    \
            _Pragma("unroll") for (int nt2 = 0; nt2 < (NTN) / 2; nt2++) {       \
                u32 ba = bb0 + nt2 * 16 * 80;                                   \
                u32 bh4[4];                                                     \
                ldsm_x4(bh4, ba);                                               \
                _Pragma("unroll") for (int half = 0; half < 2; half++) {        \
                    int nt = nt2 * 2 + half;                                    \
                    const u32* bhf = bh4 + half * 2;                            \
                    _Pragma("unroll") for (int m = 0; m < 2; m++) {             \
                        mma_f16(acc[m][nt], ahf[m], bhf);                       \
                        mma_f16(acc[m][nt], alf[m], bhf);                       \
                    }                                                           \
                }                                                               \
            }                                                                   \
        }                                                                       \
        __syncthreads();                                                        \
    }

// ---------------- generic GEMM ----------------
template<int BN, bool SPLITOUT>
__global__ __launch_bounds__(256, 2)
void mma_gemm_k(const fp16* __restrict__ Ah_, const fp16* __restrict__ Al_,
                int lda,
                const fp16* __restrict__ Bw, int ldb,
                const float* __restrict__ bias,
                float* __restrict__ C, fp16* __restrict__ Ch, fp16* __restrict__ Cl,
                int K, int Nreal)
{
    GEMM_MAINLOOP(BN, BN / 16, lda, ldb, Nreal, 0)

    auto emit = [&](int r, int n, float v) {
        if (n >= Nreal) return;
        size_t o = (size_t)r * Nreal + n;
        if (bias) v += bias[n];
        if (C) C[o] = v;
        if (SPLITOUT) split2h(v, &Ch[o], &Cl[o]);
    };
#pragma unroll
    for (int m = 0; m < 2; m++) {
        int r0 = bm + wm + m * 16 + (lane >> 2);
#pragma unroll
        for (int nt = 0; nt < BN / 16; nt++) {
            int gn = bn + wn + nt * 8 + (lane & 3) * 2;
            emit(r0,     gn,     acc[m][nt][0]);
            emit(r0,     gn + 1, acc[m][nt][1]);
            emit(r0 + 8, gn,     acc[m][nt][2]);
            emit(r0 + 8, gn + 1, acc[m][nt][3]);
        }
    }
}

// ---------------- fused recurrent GEMM + LSTM cell + q + ahp2 ----------------
// Cols [0,2048): interleaved gates (4d+g, order i,f,g,o) -> cell -> h_next.
// Cols [2048,2560): q (+b_attn). Cols [2560,3072): ahp2 = h@W_ap[:,:512]^T.
__global__ __launch_bounds__(256, 2)
void comb_cell_k(const fp16* __restrict__ Ah_, const fp16* __restrict__ Al_,
                 const fp16* __restrict__ Bw,
                 const float* __restrict__ ep,     // [VOC][2048]
                 const int* __restrict__ tgt,
                 const float* __restrict__ bq,     // bcomb
                 float* __restrict__ cst,
                 fp16* __restrict__ houth, fp16* __restrict__ houtl,
                 float* __restrict__ qout,
                 float* __restrict__ ahp2,
                 int tok_step, int noff)
{
    const int K = HD;
    GEMM_MAINLOOP(128, 8, HD, HD, NCOMB, noff)

    if (bn < 4 * HD) {
        // gate region: apply LSTM cell
#pragma unroll
        for (int m = 0; m < 2; m++) {
            int r0 = bm + wm + m * 16 + (lane >> 2);
            int r1 = r0 + 8;
            int tok0 = (tok_step == 0) ? START_TOKEN : tgt[(size_t)r0 * TT + tok_step - 1];
            int tok1 = (tok_step == 0) ? START_TOKEN : tgt[(size_t)r1 * TT + tok_step - 1];
            const float* e0 = ep + (size_t)tok0 * 4 * HD;
            const float* e1 = ep + (size_t)tok1 * 4 * HD;
#pragma unroll
            for (int nt = 0; nt < 8; nt++) {
                int gn = bn + wn + nt * 8 + (lane & 3) * 2;
                float v0 = acc[m][nt][0] + e0[gn];
                float v1 = acc[m][nt][1] + e0[gn + 1];
                float v2 = acc[m][nt][2] + e1[gn];
                float v3 = acc[m][nt][3] + e1[gn + 1];
                float p0 = __shfl_xor_sync(0xffffffffu, v0, 1);
                float p1 = __shfl_xor_sync(0xffffffffu, v1, 1);
                float p2 = __shfl_xor_sync(0xffffffffu, v2, 1);
                float p3 = __shfl_xor_sync(0xffffffffu, v3, 1);
                if (!(lane & 1)) {
                    int d = gn >> 2;
                    {
                        size_t ci = (size_t)r0 * HD + d;
                        float cn = sigmoid_fast(v1) * cst[ci]
                                 + sigmoid_fast(v0) * tanh_fast(p0);
                        cst[ci] = cn;
                        float hn = sigmoid_fast(p1) * tanh_fast(cn);
                        split2h(hn, &houth[ci], &houtl[ci]);
                    }
                    {
                        size_t ci = (size_t)r1 * HD + d;
                        float cn = sigmoid_fast(v3) * cst[ci]
                                 + sigmoid_fast(v2) * tanh_fast(p2);
                        cst[ci] = cn;
                        float hn = sigmoid_fast(p3) * tanh_fast(cn);
                        split2h(hn, &houth[ci], &houtl[ci]);
                    }
                }
            }
        }
    } else if (bn < 5 * HD) {
        // q region
#pragma unroll
        for (int m = 0; m < 2; m++) {
            int r0 = bm + wm + m * 16 + (lane >> 2);
#pragma unroll
            for (int nt = 0; nt < 8; nt++) {
                int gn = bn + wn + nt * 8 + (lane & 3) * 2;
                int qn = gn - 4 * HD;
                float b0 = bq[gn], b1 = bq[gn + 1];
                qout[(size_t)r0 * HD + qn]           = acc[m][nt][0] + b0;
                qout[(size_t)r0 * HD + qn + 1]       = acc[m][nt][1] + b1;
                qout[(size_t)(r0 + 8) * HD + qn]     = acc[m][nt][2] + b0;
                qout[(size_t)(r0 + 8) * HD + qn + 1] = acc[m][nt][3] + b1;
            }
        }
    } else {
        // ahp2 region (bias added later in attn_k)
#pragma unroll
        for (int m = 0; m < 2; m++) {
            int r0 = bm + wm + m * 16 + (lane >> 2);
#pragma unroll
            for (int nt = 0; nt < 8; nt++) {
                int gn = bn + wn + nt * 8 + (lane & 3) * 2;
                int an = gn - 5 * HD;
                ahp2[(size_t)r0 * HD + an]           = acc[m][nt][0];
                ahp2[(size_t)r0 * HD + an + 1]       = acc[m][nt][1];
                ahp2[(size_t)(r0 + 8) * HD + an]     = acc[m][nt][2];
                ahp2[(size_t)(r0 + 8) * HD + an + 1] = acc[m][nt][3];
            }
        }
    }
}

// ---------------- prep kernels ----------------
__global__ void split_arr_k(const float* __restrict__ src,
                            fp16* __restrict__ h, fp16* __restrict__ l, size_t n)
{
    for (size_t i = (size_t)blockIdx.x * blockDim.x + threadIdx.x; i < n;
         i += (size_t)gridDim.x * blockDim.x)
        split2h(src[i], &h[i], &l[i]);
}

__global__ void transpose_h_k(const float* __restrict__ src,  // [K][N]
                              fp16* __restrict__ w, int Kd, int Nd)
{
    size_t n = (size_t)Kd * Nd;
    for (size_t i = (size_t)blockIdx.x * blockDim.x + threadIdx.x; i < n;
         i += (size_t)gridDim.x * blockDim.x) {
        int k = (int)(i / Nd), nn = (int)(i % Nd);
        w[(size_t)nn * Kd + k] = __float2half(src[i]);
    }
}

// comb weight rows: n<2048 interleaved gates (src W_hh row (n&3)*512+(n>>2));
// [2048,2560): W_dec^T; [2560,3072): W_ap[n-2560][0:512]
__global__ void prep_comb_k(const float* __restrict__ W_hh,
                            const float* __restrict__ W_dec,
                            const float* __restrict__ W_ap,
                            const float* __restrict__ b_attn,
                            fp16* __restrict__ w, float* __restrict__ bc)
{
    size_t n = (size_t)NCOMB * HD;
    for (size_t i = (size_t)blockIdx.x * blockDim.x + threadIdx.x; i < n;
         i += (size_t)gridDim.x * blockDim.x) {
        int row = (int)(i / HD), k = (int)(i % HD);
        float v;
        if (row < 4 * HD) {
            int src = (row & 3) * HD + (row >> 2);
            v = W_hh[(size_t)src * HD + k];
        } else if (row < 5 * HD) {
            v = W_dec[(size_t)k * HD + (row - 4 * HD)];
        } else {
            v = W_ap[(size_t)(row - 5 * HD) * (HD + HE) + k];
        }
        w[i] = __float2half(v);
        if (i < NCOMB)
            bc[i] = (i >= 4 * HD && i < 5 * HD) ? b_attn[i - 4 * HD] : 0.0f;
    }
}

__global__ void embproj_k(const float* __restrict__ embed,
                          const float* __restrict__ W_ih,
                          const float* __restrict__ b_ih,
                          const float* __restrict__ b_hh,
                          float* __restrict__ ep)
{
    int v = blockIdx.y;
    int n = blockIdx.x * 128 + threadIdx.x;
    int j = (n & 3) * HD + (n >> 2);
    __shared__ float em[EMB];
    if (threadIdx.x < EMB) em[threadIdx.x] = embed[(size_t)v * EMB + threadIdx.x];
    __syncthreads();
    float acc = b_ih[j] + b_hh[j];
    const float* w = W_ih + (size_t)j * EMB;
#pragma unroll 8
    for (int k = 0; k < EMB; k++) acc += em[k] * w[k];
    ep[(size_t)v * 4 * HD + n] = acc;
}

__global__ void prep_outw_k(const float* __restrict__ W_out,
                            const float* __restrict__ b_out,
                            const float* __restrict__ w_copy,
                            const float* __restrict__ b_copy,
                            fp16* __restrict__ w, float* __restrict__ bo)
{
    size_t n = (size_t)121 * HD;
    for (size_t i = (size_t)blockIdx.x * blockDim.x + threadIdx.x; i < n;
         i += (size_t)gridDim.x * blockDim.x) {
        int row = (int)(i / HD), k = (int)(i % HD);
        float v = (row < VOC) ? W_out[(size_t)row * HD + k] : w_copy[k];
        w[i] = __float2half(v);
        if (i < 121) bo[i] = (i < VOC) ? b_out[i] : b_copy[0];
    }
}

// W_ap[:,512:] rows: w[n][k] = W_ap[n][512+k]  (B for ctxw GEMM, ldb=HE)
__global__ void prep_wapc_k(const float* __restrict__ W_ap, fp16* __restrict__ w)
{
    size_t n = (size_t)HD * HE;
    for (size_t i = (size_t)blockIdx.x * blockDim.x + threadIdx.x; i < n;
         i += (size_t)gridDim.x * blockDim.x) {
        int row = (int)(i / HE), k = (int)(i % HE);
        w[i] = __float2half(W_ap[(size_t)row * (HD + HE) + HD + k]);
    }
}

__global__ void conv_h_k(const float* __restrict__ src, fp16* __restrict__ dst, size_t n)
{
    for (size_t i = (size_t)blockIdx.x * blockDim.x + threadIdx.x; i < n;
         i += (size_t)gridDim.x * blockDim.x)
        dst[i] = __float2half(src[i]);
}

__global__ void encw_k(const float* __restrict__ enc,
                       const float* __restrict__ w_copy,
                       float* __restrict__ encw)
{
    int r = blockIdx.x;
    int tid = threadIdx.x;
    __shared__ float red[128];
    const float* row = enc + (size_t)r * HE;
    float acc = 0.f;
    for (int k = tid; k < HE; k += 128) acc += row[k] * w_copy[HD + k];
    red[tid] = acc;
    __syncthreads();
    for (int s2 = 64; s2; s2 >>= 1) {
        if (tid < s2) red[tid] += red[tid + s2];
        __syncthreads();
    }
    if (tid == 0) encw[r] = red[0];
}

__global__ void zero_c_k(float* __restrict__ c)
{
    size_t i = (size_t)blockIdx.x * blockDim.x + threadIdx.x;
    if (i < (size_t)BATCH * HD) c[i] = 0.0f;
}

// ---------------- attention + ah finalize ----------------
__global__ void attn_k(const float* __restrict__ encproj,
                       const float* __restrict__ ctxw,
                       const float* __restrict__ encw,
                       const float* __restrict__ q,
                       const float* __restrict__ ahp2,
                       const float* __restrict__ b_ap,
                       const float* __restrict__ v_attn,
                       float* __restrict__ attn_out,
                       fp16* __restrict__ ahh, fp16* __restrict__ ahl,  // slice t
                       float* __restrict__ ctxdot,
                       int t)
{
    int b = blockIdx.x;
    int tid = threadIdx.x;
    __shared__ __align__(16) float qsh[HD];
    __shared__ __align__(16) float vsh[HD];
    __shared__ float sc[SEQ];
    __shared__ float aprob[SEQ];

    for (int d = tid; d < HD; d += 128) {
        qsh[d] = q[(size_t)b * HD + d];
        vsh[d] = v_attn[d];
    }
    __syncthreads();

    int w = tid >> 5, lane = tid & 31;
    const float* ep = encproj + (size_t)b * SEQ * HD;
    for (int s = w; s < SEQ; s += 4) {
        float acc = 0.f;
        const float4* row4 = (const float4*)(ep + (size_t)s * HD);
#pragma unroll
        for (int j = 0; j < 4; j++) {
            int d4 = lane + j * 32;
            float4 e4 = row4[d4];
            float4 q4 = *(const float4*)&qsh[d4 * 4];
            float4 v4 = *(const float4*)&vsh[d4 * 4];
            acc += tanh_fast(e4.x + q4.x) * v4.x;
            acc += tanh_fast(e4.y + q4.y) * v4.y;
            acc += tanh_fast(e4.z + q4.z) * v4.z;
            acc += tanh_fast(e4.w + q4.w) * v4.w;
        }
#pragma unroll
        for (int o = 16; o; o >>= 1) acc += __shfl_xor_sync(0xffffffffu, acc, o);
        if (lane == 0) sc[s] = acc;
    }
    __syncthreads();

    if (tid < 32) {
        float e = (tid < SEQ) ? __expf(sc[tid]) : 0.f;
        float sum = e;
#pragma unroll
        for (int o = 16; o; o >>= 1) sum += __shfl_xor_sync(0xffffffffu, sum, o);
        float a = __fdividef(e, sum);
        float cd = 0.f;
        if (tid < SEQ) {
            aprob[tid] = a;
            attn_out[(size_t)b * TT * SEQ + (size_t)t * SEQ + tid] = a;
            cd = a * encw[(size_t)b * SEQ + tid];
        }
#pragma unroll
        for (int o = 16; o; o >>= 1) cd += __shfl_xor_sync(0xffffffffu, cd, o);
        if (tid == 0) ctxdot[(size_t)t * BATCH + b] = cd;
    }
    __syncthreads();

    // ah[d] = tanh(ahp2[d] + sum_s a_s ctxw[b,s,d] + b_ap[d]) -> fp16 split
    {
        const float4* cw4 = (const float4*)(ctxw + (size_t)b * SEQ * HD);
        float4 acc4 = *(const float4*)&ahp2[(size_t)b * HD + tid * 4];
        float4 bp4  = *(const float4*)&b_ap[tid * 4];
        acc4.x += bp4.x; acc4.y += bp4.y; acc4.z += bp4.z; acc4.w += bp4.w;
#pragma unroll
        for (int s = 0; s < SEQ; s++) {
            float a = aprob[s];
            float4 v = cw4[s * (HD / 4) + tid];
            acc4.x += a * v.x; acc4.y += a * v.y;
            acc4.z += a * v.z; acc4.w += a * v.w;
        }
        size_t o = (size_t)b * HD + tid * 4;
        split2h(tanh_fast(acc4.x), &ahh[o],     &ahl[o]);
        split2h(tanh_fast(acc4.y), &ahh[o + 1], &ahl[o + 1]);
        split2h(tanh_fast(acc4.z), &ahh[o + 2], &ahl[o + 2]);
        split2h(tanh_fast(acc4.w), &ahh[o + 3], &ahl[o + 3]);
    }
}

// ---------------- output mix: warp per (t,b) row ----------------
__global__ void out2_k(const float* __restrict__ logits_all,
                       const float* __restrict__ ctxdot,
                       const int* __restrict__ input_char_ids,
                       const float* __restrict__ attn_base,
                       float* __restrict__ outputs)
{
    int warp = threadIdx.x >> 5, lane = threadIdx.x & 31;
    int row = blockIdx.x * 4 + warp;
    int t = row >> 12;
    int b = row & 4095;
    __shared__ float cbuf[4][VOC];

    for (int k = lane; k < VOC; k += 32) cbuf[warp][k] = 0.f;
    __syncwarp();
    if (lane < SEQ) {
        int id = input_char_ids[(size_t)b * SEQ + lane];
        float a = attn_base[(size_t)b * TT * SEQ + (size_t)t * SEQ + lane];
        atomicAdd(&cbuf[warp][id], a);
    }
    __syncwarp();

    const float* lrow = logits_all + (size_t)row * 121;
    float p = sigmoid_fast(lrow[120] + ctxdot[row]);

    float e[4];
    float sum = 0.f;
#pragma unroll
    for (int j = 0; j < 4; j++) {
        int idx = lane + j * 32;
        e[j] = (idx < VOC) ? __expf(lrow[idx]) : 0.f;
        sum += e[j];
    }
#pragma unroll
    for (int o = 16; o; o >>= 1) sum += __shfl_xor_sync(0xffffffffu, sum, o);
    float inv = __fdividef(1.0f - p, sum);
#pragma unroll
    for (int j = 0; j < 4; j++) {
        int idx = lane + j * 32;
        if (idx < VOC)
            outputs[(size_t)b * TT * VOC + (size_t)t * VOC + idx] =
                inv * e[j] + p * cbuf[warp][idx];
    }
}

// ---------------- host ----------------
#define SYM(p, s) cudaGetSymbolAddress((void**)&(p), s)
#define SM128 61440
#define SM64  51200

extern "C" void kernel_launch(void* const* d_in, const int* in_sizes, int n_in,
                              void* d_out, int out_size)
{
    (void)in_sizes; (void)n_in; (void)out_size;
    const float* enc        = (const float*)d_in[0];
    const float* enc_final  = (const float*)d_in[1];
    const int*   tgt        = (const int*)d_in[2];
    const int*   input_ids  = (const int*)d_in[3];
    const float* embed      = (const float*)d_in[4];
    const float* W_init     = (const float*)d_in[5];
    const float* b_init     = (const float*)d_in[6];
    const float* W_ih       = (const float*)d_in[7];
    const float* W_hh       = (const float*)d_in[8];
    const float* b_ih       = (const float*)d_in[9];
    const float* b_hh       = (const float*)d_in[10];
    const float* W_enc_attn = (const float*)d_in[11];
    const float* W_dec_attn = (const float*)d_in[12];
    const float* b_attn     = (const float*)d_in[13];
    const float* v_attn     = (const float*)d_in[14];
    const float* W_ap       = (const float*)d_in[15];
    const float* b_ap       = (const float*)d_in[16];
    const float* W_out      = (const float*)d_in[17];
    const float* b_out      = (const float*)d_in[18];
    const float* w_copy     = (const float*)d_in[19];
    const float* b_copy     = (const float*)d_in[20];

    float* out = (float*)d_out;
    float* outputs   = out;
    float* attn_base = out + (size_t)BATCH * TT * VOC;

    fp16 *ench, *encl, *efh, *efl, *wcomb, *we, *wapc, *woc, *wi;
    fp16 *hh0, *hl0, *hh1, *hl1, *ahh, *ahl;
    float *encproj, *ctxwp, *encw, *embproj, *bcomb, *boc, *cst;
    float *q, *ahp2, *logits_all, *ctxdot;
    SYM(ench, g_ench); SYM(encl, g_encl);
    SYM(efh, g_efh);   SYM(efl, g_efl);
    SYM(encproj, g_encproj); SYM(ctxwp, g_ctxw); SYM(encw, g_encw);
    SYM(embproj, g_embproj);
    SYM(wcomb, g_wcomb); SYM(bcomb, g_bcomb);
    SYM(we, g_we);     SYM(wapc, g_wapc);
    SYM(woc, g_woc);   SYM(boc, g_boc);
    SYM(wi, g_wi);
    SYM(hh0, g_hh0);   SYM(hl0, g_hl0);
    SYM(hh1, g_hh1);   SYM(hl1, g_hl1);
    SYM(cst, g_c);     SYM(q, g_q); SYM(ahp2, g_ahp2);
    SYM(ahh, g_ahh_all); SYM(ahl, g_ahl_all);
    SYM(logits_all, g_logits_all); SYM(ctxdot, g_ctxdot);

    fp16* hbh[2] = {hh0, hh1};
    fp16* hbl[2] = {hl0, hl1};

    cudaFuncSetAttribute(mma_gemm_k<128, false>,
                         cudaFuncAttributeMaxDynamicSharedMemorySize, SM128);
    cudaFuncSetAttribute(mma_gemm_k<64, true>,
                         cudaFuncAttributeMaxDynamicSharedMemorySize, SM64);
    cudaFuncSetAttribute(comb_cell_k,
                         cudaFuncAttributeMaxDynamicSharedMemorySize, SM128);

    // ---- prep ----
    split_arr_k<<<4096, 256>>>(enc, ench, encl, (size_t)BATCH * SEQ * HE);
    split_arr_k<<<2048, 256>>>(enc_final, efh, efl, (size_t)BATCH * HE);
    embproj_k<<<dim3(16, VOC), 128>>>(embed, W_ih, b_ih, b_hh, embproj);
    prep_comb_k<<<2048, 256>>>(W_hh, W_dec_attn, W_ap, b_attn, wcomb, bcomb);
    transpose_h_k<<<1024, 256>>>(W_enc_attn, we, HE, HD);
    prep_wapc_k<<<1024, 256>>>(W_ap, wapc);
    prep_outw_k<<<256, 256>>>(W_out, b_out, w_copy, b_copy, woc, boc);
    conv_h_k<<<1024, 256>>>(W_init, wi, (size_t)HD * HE);
    encw_k<<<BATCH * SEQ, 128>>>(enc, w_copy, encw);
    zero_c_k<<<(BATCH * HD + 255) / 256, 256>>>(cst);

    // h^{-1} = enc_final @ W_init^T + b_init
    mma_gemm_k<64, true><<<dim3(8, 32), 256, SM64>>>(
        efh, efl, HE, wi, HE, b_init,
        nullptr, hh0, hl0, HE, HD);
    // enc_proj = enc @ W_enc_attn ; ctxw = enc @ W_ap[:,512:]^T
    mma_gemm_k<128, false><<<dim3(4, 768), 256, SM128>>>(
        ench, encl, HE, we, HE, nullptr,
        encproj, nullptr, nullptr, HE, HD);
    mma_gemm_k<128, false><<<dim3(4, 768), 256, SM128>>>(
        ench, encl, HE, wapc, HE, nullptr,
        ctxwp, nullptr, nullptr, HE, HD);

    // prologue: gates^0 from h^{-1} -> h^0 in buf1
    comb_cell_k<<<dim3(16, 32), 256, SM128>>>(
        hh0, hl0, wcomb, embproj, tgt, bcomb,
        cst, hh1, hl1, q, ahp2, /*tok_step=*/0, /*noff=*/0);

    for (int t = 0; t < TT; t++) {
        int cur = (t + 1) & 1;   // h^t
        int nxt = t & 1;
        if (t < TT - 1) {
            comb_cell_k<<<dim3(24, 32), 256, SM128>>>(
                hbh[cur], hbl[cur], wcomb, embproj, tgt, bcomb,
                cst, hbh[nxt], hbl[nxt], q, ahp2, t + 1, 0);
        } else {
            comb_cell_k<<<dim3(8, 32), 256, SM128>>>(
                hbh[cur], hbl[cur], wcomb, embproj, tgt, bcomb,
                cst, nullptr, nullptr, q, ahp2, 0, 16);
        }
        attn_k<<<BATCH, 128>>>(encproj, ctxwp, encw, q, ahp2, b_ap, v_attn,
                               attn_base,
                               ahh + (size_t)t * BATCH * HD,
                               ahl + (size_t)t * BATCH * HD,
                               ctxdot, t);
    }

    // deferred logits+copy GEMM: M = T*B, N = 121, K = 512
    mma_gemm_k<128, false><<<dim3(1, (TT * BATCH) / 128), 256, SM128>>>(
        ahh, ahl, HD, woc, HD, boc,
        logits_all, nullptr, nullptr, HD, 121);
    out2_k<<<TT * BATCH / 4, 128>>>(logits_all, ctxdot, input_ids, attn_base, outputs);
}

// round 8
// speedup vs baseline: 2.0419x; 1.0971x over previous
#include <cuda_runtime.h>
#include <cuda_fp16.h>
#include <cstdint>

#define BATCH 4096
#define SEQ   24
#define TT    32
#define VOC   120
#define EMB   128
#define HE    512
#define HD    512
#define START_TOKEN 2
#define NCOMB 3072   // 2048 interleaved gates + 512 q + 512 ahp2

typedef __half fp16;
typedef unsigned int u32;

// ---------------- device scratch ----------------
__device__ __align__(256) fp16 g_ench[(size_t)BATCH * SEQ * HE];
__device__ __align__(256) fp16 g_encl[(size_t)BATCH * SEQ * HE];
__device__ __align__(256) fp16 g_efh[(size_t)BATCH * HE];
__device__ __align__(256) fp16 g_efl[(size_t)BATCH * HE];
__device__ __align__(256) float g_encproj[(size_t)BATCH * SEQ * HD];
__device__ __align__(256) float g_ctxw[(size_t)BATCH * SEQ * HD];
__device__ __align__(256) float g_encw[(size_t)BATCH * SEQ];
__device__ __align__(256) float g_embproj[(size_t)VOC * 4 * HD];   // [tok][4d+g]
// weights (single fp16)
__device__ __align__(256) fp16 g_wcomb[(size_t)NCOMB * HD];
__device__ __align__(256) float g_bcomb[NCOMB];
__device__ __align__(256) fp16 g_we[(size_t)HE * HD];
__device__ __align__(256) fp16 g_wapc[(size_t)HD * HE];    // W_ap[:,512:] rows
__device__ __align__(256) fp16 g_woc[(size_t)121 * HD];
__device__ __align__(256) float g_boc[121];
__device__ __align__(256) fp16 g_wi[(size_t)HD * HE];
// activations (h double-buffered, fp16 hi/lo)
__device__ __align__(256) fp16 g_hh0[(size_t)BATCH * HD];
__device__ __align__(256) fp16 g_hl0[(size_t)BATCH * HD];
__device__ __align__(256) fp16 g_hh1[(size_t)BATCH * HD];
__device__ __align__(256) fp16 g_hl1[(size_t)BATCH * HD];
__device__ __align__(256) float g_c[(size_t)BATCH * HD];
__device__ __align__(256) float g_q[(size_t)BATCH * HD];
__device__ __align__(256) float g_ahp2a[(size_t)TT * BATCH * HD];  // per-step ahp2
__device__ __align__(256) fp16 g_ahh_all[(size_t)TT * BATCH * HD];
__device__ __align__(256) fp16 g_ahl_all[(size_t)TT * BATCH * HD];
__device__ __align__(256) float g_logits_all[(size_t)TT * BATCH * 121];
__device__ __align__(256) float g_ctxdot[(size_t)TT * BATCH];

// ---------------- math helpers ----------------
__device__ __forceinline__ float tanh_fast(float x) {
    float e = __expf(2.0f * x);
    return 1.0f - __fdividef(2.0f, e + 1.0f);
}
__device__ __forceinline__ float sigmoid_fast(float x) {
    return __fdividef(1.0f, 1.0f + __expf(-x));
}
__device__ __forceinline__ void split2h(float v, fp16* hi, fp16* lo) {
    fp16 h = __float2half(v);
    *hi = h;
    *lo = __float2half(v - __half2float(h));
}

// ---------------- PTX helpers ----------------
__device__ __forceinline__ u32 smem_u32(const void* p) {
    u32 a;
    asm("{ .reg .u64 t; cvta.to.shared.u64 t, %1; cvt.u32.u64 %0, t; }"
        : "=r"(a) : "l"(p));
    return a;
}
__device__ __forceinline__ void cp16(u32 d, const void* s, u32 sz) {
    asm volatile("cp.async.cg.shared.global [%0], [%1], 16, %2;"
                 :: "r"(d), "l"(s), "r"(sz) : "memory");
}
__device__ __forceinline__ void cp_commit() {
    asm volatile("cp.async.commit_group;" ::: "memory");
}
template<int N>
__device__ __forceinline__ void cp_wait() {
    asm volatile("cp.async.wait_group %0;" :: "n"(N) : "memory");
}
__device__ __forceinline__ void ldsm_x4(u32* r, u32 a) {
    asm volatile("ldmatrix.sync.aligned.m8n8.x4.shared.b16 {%0,%1,%2,%3}, [%4];"
                 : "=r"(r[0]), "=r"(r[1]), "=r"(r[2]), "=r"(r[3]) : "r"(a));
}
__device__ __forceinline__ void mma_f16(float* c, const u32* a, const u32* b) {
    asm volatile(
        "mma.sync.aligned.m16n8k16.row.col.f32.f16.f16.f32 "
        "{%0,%1,%2,%3}, {%4,%5,%6,%7}, {%8,%9}, {%0,%1,%2,%3};"
        : "+f"(c[0]), "+f"(c[1]), "+f"(c[2]), "+f"(c[3])
        : "r"(a[0]), "r"(a[1]), "r"(a[2]), "r"(a[3]), "r"(b[0]), "r"(b[1]));
}

// ======== GEMM mainloop: A fp16 hi/lo pair, B single fp16 ========
// per-buffer: Ah@0 Al@10240 B@20480 (BN*80 bytes); row stride 80 B.

#define GEMM_MAINLOOP(BN, NTN, LDA, LDB, NREAL, BNOFF)                          \
    constexpr int BUFB = 20480 + (BN) * 80;                                     \
    extern __shared__ char smem[];                                              \
    const u32 sb = smem_u32(smem);                                              \
    const int tid = threadIdx.x, lane = tid & 31, wid = tid >> 5;               \
    const int bm = blockIdx.y * 128, bn = (blockIdx.x + (BNOFF)) * (BN);        \
    const int wm = (wid >> 1) * 32, wn = (wid & 1) * ((BN) / 2);                \
    float acc[2][NTN][4];                                                       \
    _Pragma("unroll") for (int m = 0; m < 2; m++)                               \
    _Pragma("unroll") for (int n = 0; n < NTN; n++)                             \
    _Pragma("unroll") for (int j = 0; j < 4; j++) acc[m][n][j] = 0.0f;          \
    const int nch = K / 32;                                                     \
    auto stage = [&](int c) {                                                   \
        const int kt = c * 32;                                                  \
        const u32 bufb = sb + (u32)(c & 1) * BUFB;                              \
        _Pragma("unroll") for (int p = 0; p < 2; p++) {                         \
            int v = tid + p * 256, row = v >> 2, g = v & 3;                     \
            size_t go = (size_t)(bm + row) * (LDA) + kt + g * 8;                \
            u32 sa = bufb + row * 80 + g * 16;                                  \
            cp16(sa, Ah_ + go, 16);                                             \
            cp16(sa + 10240, Al_ + go, 16);                                     \
        }                                                                       \
        _Pragma("unroll") for (int p = 0; p < (BN) / 64; p++) {                 \
            int v = tid + p * 256, row = v >> 2, g = v & 3;                     \
            int n = bn + row;                                                   \
            int na = (n < (NREAL)) ? n : ((NREAL) - 1);                         \
            u32 sz = (n < (NREAL)) ? 16u : 0u;                                  \
            size_t go = (size_t)na * (LDB) + kt + g * 8;                        \
            u32 sa = bufb + 20480 + row * 80 + g * 16;                          \
            cp16(sa, Bw + go, sz);                                              \
        }                                                                       \
    };                                                                          \
    stage(0);                                                                   \
    cp_commit();                                                                \
    for (int c = 0; c < nch; c++) {                                             \
        if (c + 1 < nch) { stage(c + 1); cp_commit(); cp_wait<1>(); }           \
        else             { cp_wait<0>(); }                                      \
        __syncthreads();                                                        \
        const u32 bufb = sb + (u32)(c & 1) * BUFB;                              \
        _Pragma("unroll") for (int k2 = 0; k2 < 2; k2++) {                      \
            const u32 kb = k2 * 32;                                             \
            const u32 a0 = bufb + (wm + (lane & 15)) * 80 + kb + (lane >> 4) * 16; \
            const u32 a1 = a0 + 16 * 80;                                        \
            u32 ahf[2][4], alf[2][4];                                           \
            ldsm_x4(ahf[0], a0); ldsm_x4(ahf[1], a1);                           \
            ldsm_x4(alf[0], a0 + 10240); ldsm_x4(alf[1], a1 + 10240);           \
            const u32 bb0 = bufb + 20480 +                                      \
                (wn + (lane & 7) + ((lane >> 4) & 1) * 8) * 80 +                \
                kb + ((lane >> 3) & 1) * 16;                                    \
            _Pragma("unroll") for (int nt2 = 0; nt2 < (NTN) / 2; nt2++) {       \
                u32 ba = bb0 + nt2 * 16 * 80;                                   \
                u32 bh4[4];                                                     \
                ldsm_x4(bh4, ba);                                               \
                _Pragma("unroll") for (int half = 0; half < 2; half++) {        \
                    int nt = nt2 * 2 + half;                                    \
                    const u32* bhf = bh4 + half * 2;                            \
                    _Pragma("unroll") for (int m = 0; m < 2; m++) {             \
                        mma_f16(acc[m][nt], ahf[m], bhf);                       \
                        mma_f16(acc[m][nt], alf[m], bhf);                       \
                    }                                                           \
                }                                                               \
            }                                                                   \
        }                                                                       \
        __syncthreads();                                                        \
    }

// ---------------- generic GEMM ----------------
template<int BN, bool SPLITOUT>
__global__ __launch_bounds__(256, 2)
void mma_gemm_k(const fp16* __restrict__ Ah_, const fp16* __restrict__ Al_,
                int lda,
                const fp16* __restrict__ Bw, int ldb,
                const float* __restrict__ bias,
                float* __restrict__ C, fp16* __restrict__ Ch, fp16* __restrict__ Cl,
                int K, int Nreal)
{
    GEMM_MAINLOOP(BN, BN / 16, lda, ldb, Nreal, 0)

    auto emit = [&](int r, int n, float v) {
        if (n >= Nreal) return;
        size_t o = (size_t)r * Nreal + n;
        if (bias) v += bias[n];
        if (C) C[o] = v;
        if (SPLITOUT) split2h(v, &Ch[o], &Cl[o]);
    };
#pragma unroll
    for (int m = 0; m < 2; m++) {
        int r0 = bm + wm + m * 16 + (lane >> 2);
#pragma unroll
        for (int nt = 0; nt < BN / 16; nt++) {
            int gn = bn + wn + nt * 8 + (lane & 3) * 2;
            emit(r0,     gn,     acc[m][nt][0]);
            emit(r0,     gn + 1, acc[m][nt][1]);
            emit(r0 + 8, gn,     acc[m][nt][2]);
            emit(r0 + 8, gn + 1, acc[m][nt][3]);
        }
    }
}

// ---------------- fused recurrent GEMM + LSTM cell + q + ahp2 ----------------
__global__ __launch_bounds__(256, 2)
void comb_cell_k(const fp16* __restrict__ Ah_, const fp16* __restrict__ Al_,
                 const fp16* __restrict__ Bw,
                 const float* __restrict__ ep,     // [VOC][2048]
                 const int* __restrict__ tgt,
                 const float* __restrict__ bq,     // bcomb
                 float* __restrict__ cst,
                 fp16* __restrict__ houth, fp16* __restrict__ houtl,
                 float* __restrict__ qout,
                 float* __restrict__ ahp2,         // per-step slice
                 int tok_step, int noff)
{
    const int K = HD;
    GEMM_MAINLOOP(128, 8, HD, HD, NCOMB, noff)

    if (bn < 4 * HD) {
#pragma unroll
        for (int m = 0; m < 2; m++) {
            int r0 = bm + wm + m * 16 + (lane >> 2);
            int r1 = r0 + 8;
            int tok0 = (tok_step == 0) ? START_TOKEN : tgt[(size_t)r0 * TT + tok_step - 1];
            int tok1 = (tok_step == 0) ? START_TOKEN : tgt[(size_t)r1 * TT + tok_step - 1];
            const float* e0 = ep + (size_t)tok0 * 4 * HD;
            const float* e1 = ep + (size_t)tok1 * 4 * HD;
#pragma unroll
            for (int nt = 0; nt < 8; nt++) {
                int gn = bn + wn + nt * 8 + (lane & 3) * 2;
                float v0 = acc[m][nt][0] + e0[gn];
                float v1 = acc[m][nt][1] + e0[gn + 1];
                float v2 = acc[m][nt][2] + e1[gn];
                float v3 = acc[m][nt][3] + e1[gn + 1];
                float p0 = __shfl_xor_sync(0xffffffffu, v0, 1);
                float p1 = __shfl_xor_sync(0xffffffffu, v1, 1);
                float p2 = __shfl_xor_sync(0xffffffffu, v2, 1);
                float p3 = __shfl_xor_sync(0xffffffffu, v3, 1);
                if (!(lane & 1)) {
                    int d = gn >> 2;
                    {
                        size_t ci = (size_t)r0 * HD + d;
                        float cn = sigmoid_fast(v1) * cst[ci]
                                 + sigmoid_fast(v0) * tanh_fast(p0);
                        cst[ci] = cn;
                        float hn = sigmoid_fast(p1) * tanh_fast(cn);
                        split2h(hn, &houth[ci], &houtl[ci]);
                    }
                    {
                        size_t ci = (size_t)r1 * HD + d;
                        float cn = sigmoid_fast(v3) * cst[ci]
                                 + sigmoid_fast(v2) * tanh_fast(p2);
                        cst[ci] = cn;
                        float hn = sigmoid_fast(p3) * tanh_fast(cn);
                        split2h(hn, &houth[ci], &houtl[ci]);
                    }
                }
            }
        }
    } else if (bn < 5 * HD) {
#pragma unroll
        for (int m = 0; m < 2; m++) {
            int r0 = bm + wm + m * 16 + (lane >> 2);
#pragma unroll
            for (int nt = 0; nt < 8; nt++) {
                int gn = bn + wn + nt * 8 + (lane & 3) * 2;
                int qn = gn - 4 * HD;
                float b0 = bq[gn], b1 = bq[gn + 1];
                qout[(size_t)r0 * HD + qn]           = acc[m][nt][0] + b0;
                qout[(size_t)r0 * HD + qn + 1]       = acc[m][nt][1] + b1;
                qout[(size_t)(r0 + 8) * HD + qn]     = acc[m][nt][2] + b0;
                qout[(size_t)(r0 + 8) * HD + qn + 1] = acc[m][nt][3] + b1;
            }
        }
    } else {
#pragma unroll
        for (int m = 0; m < 2; m++) {
            int r0 = bm + wm + m * 16 + (lane >> 2);
#pragma unroll
            for (int nt = 0; nt < 8; nt++) {
                int gn = bn + wn + nt * 8 + (lane & 3) * 2;
                int an = gn - 5 * HD;
                ahp2[(size_t)r0 * HD + an]           = acc[m][nt][0];
                ahp2[(size_t)r0 * HD + an + 1]       = acc[m][nt][1];
                ahp2[(size_t)(r0 + 8) * HD + an]     = acc[m][nt][2];
                ahp2[(size_t)(r0 + 8) * HD + an + 1] = acc[m][nt][3];
            }
        }
    }
}

// ---------------- prep kernels ----------------
__global__ void split_arr_k(const float* __restrict__ src,
                            fp16* __restrict__ h, fp16* __restrict__ l, size_t n)
{
    for (size_t i = (size_t)blockIdx.x * blockDim.x + threadIdx.x; i < n;
         i += (size_t)gridDim.x * blockDim.x)
        split2h(src[i], &h[i], &l[i]);
}

__global__ void transpose_h_k(const float* __restrict__ src,  // [K][N]
                              fp16* __restrict__ w, int Kd, int Nd)
{
    size_t n = (size_t)Kd * Nd;
    for (size_t i = (size_t)blockIdx.x * blockDim.x + threadIdx.x; i < n;
         i += (size_t)gridDim.x * blockDim.x) {
        int k = (int)(i / Nd), nn = (int)(i % Nd);
        w[(size_t)nn * Kd + k] = __float2half(src[i]);
    }
}

__global__ void prep_comb_k(const float* __restrict__ W_hh,
                            const float* __restrict__ W_dec,
                            const float* __restrict__ W_ap,
                            const float* __restrict__ b_attn,
                            fp16* __restrict__ w, float* __restrict__ bc)
{
    size_t n = (size_t)NCOMB * HD;
    for (size_t i = (size_t)blockIdx.x * blockDim.x + threadIdx.x; i < n;
         i += (size_t)gridDim.x * blockDim.x) {
        int row = (int)(i / HD), k = (int)(i % HD);
        float v;
        if (row < 4 * HD) {
            int src = (row & 3) * HD + (row >> 2);
            v = W_hh[(size_t)src * HD + k];
        } else if (row < 5 * HD) {
            v = W_dec[(size_t)k * HD + (row - 4 * HD)];
        } else {
            v = W_ap[(size_t)(row - 5 * HD) * (HD + HE) + k];
        }
        w[i] = __float2half(v);
        if (i < NCOMB)
            bc[i] = (i >= 4 * HD && i < 5 * HD) ? b_attn[i - 4 * HD] : 0.0f;
    }
}

__global__ void embproj_k(const float* __restrict__ embed,
                          const float* __restrict__ W_ih,
                          const float* __restrict__ b_ih,
                          const float* __restrict__ b_hh,
                          float* __restrict__ ep)
{
    int v = blockIdx.y;
    int n = blockIdx.x * 128 + threadIdx.x;
    int j = (n & 3) * HD + (n >> 2);
    __shared__ float em[EMB];
    if (threadIdx.x < EMB) em[threadIdx.x] = embed[(size_t)v * EMB + threadIdx.x];
    __syncthreads();
    float acc = b_ih[j] + b_hh[j];
    const float* w = W_ih + (size_t)j * EMB;
#pragma unroll 8
    for (int k = 0; k < EMB; k++) acc += em[k] * w[k];
    ep[(size_t)v * 4 * HD + n] = acc;
}

__global__ void prep_outw_k(const float* __restrict__ W_out,
                            const float* __restrict__ b_out,
                            const float* __restrict__ w_copy,
                            const float* __restrict__ b_copy,
                            fp16* __restrict__ w, float* __restrict__ bo)
{
    size_t n = (size_t)121 * HD;
    for (size_t i = (size_t)blockIdx.x * blockDim.x + threadIdx.x; i < n;
         i += (size_t)gridDim.x * blockDim.x) {
        int row = (int)(i / HD), k = (int)(i % HD);
        float v = (row < VOC) ? W_out[(size_t)row * HD + k] : w_copy[k];
        w[i] = __float2half(v);
        if (i < 121) bo[i] = (i < VOC) ? b_out[i] : b_copy[0];
    }
}

__global__ void prep_wapc_k(const float* __restrict__ W_ap, fp16* __restrict__ w)
{
    size_t n = (size_t)HD * HE;
    for (size_t i = (size_t)blockIdx.x * blockDim.x + threadIdx.x; i < n;
         i += (size_t)gridDim.x * blockDim.x) {
        int row = (int)(i / HE), k = (int)(i % HE);
        w[i] = __float2half(W_ap[(size_t)row * (HD + HE) + HD + k]);
    }
}

__global__ void conv_h_k(const float* __restrict__ src, fp16* __restrict__ dst, size_t n)
{
    for (size_t i = (size_t)blockIdx.x * blockDim.x + threadIdx.x; i < n;
         i += (size_t)gridDim.x * blockDim.x)
        dst[i] = __float2half(src[i]);
}

__global__ void encw_k(const float* __restrict__ enc,
                       const float* __restrict__ w_copy,
                       float* __restrict__ encw)
{
    int r = blockIdx.x;
    int tid = threadIdx.x;
    __shared__ float red[128];
    const float* row = enc + (size_t)r * HE;
    float acc = 0.f;
    for (int k = tid; k < HE; k += 128) acc += row[k] * w_copy[HD + k];
    red[tid] = acc;
    __syncthreads();
    for (int s2 = 64; s2; s2 >>= 1) {
        if (tid < s2) red[tid] += red[tid + s2];
        __syncthreads();
    }
    if (tid == 0) encw[r] = red[0];
}

__global__ void zero_c_k(float* __restrict__ c)
{
    size_t i = (size_t)blockIdx.x * blockDim.x + threadIdx.x;
    if (i < (size_t)BATCH * HD) c[i] = 0.0f;
}

// ---------------- per-step attention scores only ----------------
__global__ void attn_score_k(const float* __restrict__ encproj,
                             const float* __restrict__ q,
                             const float* __restrict__ v_attn,
                             float* __restrict__ attn_out,   // [b][t][s]
                             int t)
{
    int b = blockIdx.x;
    int tid = threadIdx.x;
    __shared__ __align__(16) float qsh[HD];
    __shared__ __align__(16) float vsh[HD];
    __shared__ float sc[SEQ];

    for (int d = tid; d < HD; d += 128) {
        qsh[d] = q[(size_t)b * HD + d];
        vsh[d] = v_attn[d];
    }
    __syncthreads();

    int w = tid >> 5, lane = tid & 31;
    const float* ep = encproj + (size_t)b * SEQ * HD;
    for (int s = w; s < SEQ; s += 4) {
        float acc = 0.f;
        const float4* row4 = (const float4*)(ep + (size_t)s * HD);
#pragma unroll
        for (int j = 0; j < 4; j++) {
            int d4 = lane + j * 32;
            float4 e4 = row4[d4];
            float4 q4 = *(const float4*)&qsh[d4 * 4];
            float4 v4 = *(const float4*)&vsh[d4 * 4];
            acc += tanh_fast(e4.x + q4.x) * v4.x;
            acc += tanh_fast(e4.y + q4.y) * v4.y;
            acc += tanh_fast(e4.z + q4.z) * v4.z;
            acc += tanh_fast(e4.w + q4.w) * v4.w;
        }
#pragma unroll
        for (int o = 16; o; o >>= 1) acc += __shfl_xor_sync(0xffffffffu, acc, o);
        if (lane == 0) sc[s] = acc;
    }
    __syncthreads();

    if (tid < 32) {
        float e = (tid < SEQ) ? __expf(sc[tid]) : 0.f;
        float sum = e;
#pragma unroll
        for (int o = 16; o; o >>= 1) sum += __shfl_xor_sync(0xffffffffu, sum, o);
        if (tid < SEQ)
            attn_out[(size_t)b * TT * SEQ + (size_t)t * SEQ + tid] =
                __fdividef(e, sum);
    }
}

// ---------------- deferred batched ctx pass ----------------
// block per b; smem: ctxw[b] (SEQ*HD), aprob (TT*SEQ), encw (SEQ).
// ah_all[t,b,d] = tanh(ahp2a[t,b,d] + sum_s a[t,s]*ctxw[b,s,d] + b_ap[d])
// ctxdot[t,b]   = sum_s a[t,s]*encw[b,s]
#define CTXB_SMEM ((SEQ * HD + TT * SEQ + SEQ) * 4)
__global__ __launch_bounds__(256)
void ctx_batch_k(const float* __restrict__ ctxw,
                 const float* __restrict__ encw,
                 const float* __restrict__ aprob,    // attn_base [b][t][s]
                 const float* __restrict__ ahp2a,    // [t][b][d]
                 const float* __restrict__ b_ap,
                 fp16* __restrict__ ahh, fp16* __restrict__ ahl,
                 float* __restrict__ ctxdot)
{
    int b = blockIdx.x;
    int tid = threadIdx.x;
    extern __shared__ float sm[];
    float* cw = sm;                 // [SEQ*HD]
    float* ap = sm + SEQ * HD;      // [TT*SEQ]
    float* ew = ap + TT * SEQ;      // [SEQ]

    {
        const float4* src = (const float4*)(ctxw + (size_t)b * SEQ * HD);
        float4* dst = (float4*)cw;
        for (int i = tid; i < SEQ * HD / 4; i += 256) dst[i] = src[i];
    }
    for (int i = tid; i < TT * SEQ; i += 256)
        ap[i] = aprob[(size_t)b * TT * SEQ + i];
    if (tid < SEQ) ew[tid] = encw[(size_t)b * SEQ + tid];
    __syncthreads();

    if (tid < TT) {
        float cd = 0.f;
#pragma unroll
        for (int s = 0; s < SEQ; s++) cd += ap[tid * SEQ + s] * ew[s];
        ctxdot[(size_t)tid * BATCH + b] = cd;
    }

    float bap0 = b_ap[tid], bap1 = b_ap[tid + 256];
    for (int t = 0; t < TT; t++) {
        float a0 = 0.f, a1 = 0.f;
        const float* apt = ap + t * SEQ;
#pragma unroll
        for (int s = 0; s < SEQ; s++) {
            float a = apt[s];
            a0 += a * cw[s * HD + tid];
            a1 += a * cw[s * HD + tid + 256];
        }
        size_t base = (size_t)t * BATCH * HD + (size_t)b * HD;
        float v0 = tanh_fast(ahp2a[base + tid] + a0 + bap0);
        float v1 = tanh_fast(ahp2a[base + tid + 256] + a1 + bap1);
        split2h(v0, &ahh[base + tid],       &ahl[base + tid]);
        split2h(v1, &ahh[base + tid + 256], &ahl[base + tid + 256]);
    }
}

// ---------------- output mix: warp per (t,b) row ----------------
__global__ void out2_k(const float* __restrict__ logits_all,
                       const float* __restrict__ ctxdot,
                       const int* __restrict__ input_char_ids,
                       const float* __restrict__ attn_base,
                       float* __restrict__ outputs)
{
    int warp = threadIdx.x >> 5, lane = threadIdx.x & 31;
    int row = blockIdx.x * 4 + warp;
    int t = row >> 12;
    int b = row & 4095;
    __shared__ float cbuf[4][VOC];

    for (int k = lane; k < VOC; k += 32) cbuf[warp][k] = 0.f;
    __syncwarp();
    if (lane < SEQ) {
        int id = input_char_ids[(size_t)b * SEQ + lane];
        float a = attn_base[(size_t)b * TT * SEQ + (size_t)t * SEQ + lane];
        atomicAdd(&cbuf[warp][id], a);
    }
    __syncwarp();

    const float* lrow = logits_all + (size_t)row * 121;
    float p = sigmoid_fast(lrow[120] + ctxdot[row]);

    float e[4];
    float sum = 0.f;
#pragma unroll
    for (int j = 0; j < 4; j++) {
        int idx = lane + j * 32;
        e[j] = (idx < VOC) ? __expf(lrow[idx]) : 0.f;
        sum += e[j];
    }
#pragma unroll
    for (int o = 16; o; o >>= 1) sum += __shfl_xor_sync(0xffffffffu, sum, o);
    float inv = __fdividef(1.0f - p, sum);
#pragma unroll
    for (int j = 0; j < 4; j++) {
        int idx = lane + j * 32;
        if (idx < VOC)
            outputs[(size_t)b * TT * VOC + (size_t)t * VOC + idx] =
                inv * e[j] + p * cbuf[warp][idx];
    }
}

// ---------------- host ----------------
#define SYM(p, s) cudaGetSymbolAddress((void**)&(p), s)
#define SM128 61440
#define SM64  51200

extern "C" void kernel_launch(void* const* d_in, const int* in_sizes, int n_in,
                              void* d_out, int out_size)
{
    (void)in_sizes; (void)n_in; (void)out_size;
    const float* enc        = (const float*)d_in[0];
    const float* enc_final  = (const float*)d_in[1];
    const int*   tgt        = (const int*)d_in[2];
    const int*   input_ids  = (const int*)d_in[3];
    const float* embed      = (const float*)d_in[4];
    const float* W_init     = (const float*)d_in[5];
    const float* b_init     = (const float*)d_in[6];
    const float* W_ih       = (const float*)d_in[7];
    const float* W_hh       = (const float*)d_in[8];
    const float* b_ih       = (const float*)d_in[9];
    const float* b_hh       = (const float*)d_in[10];
    const float* W_enc_attn = (const float*)d_in[11];
    const float* W_dec_attn = (const float*)d_in[12];
    const float* b_attn     = (const float*)d_in[13];
    const float* v_attn     = (const float*)d_in[14];
    const float* W_ap       = (const float*)d_in[15];
    const float* b_ap       = (const float*)d_in[16];
    const float* W_out      = (const float*)d_in[17];
    const float* b_out      = (const float*)d_in[18];
    const float* w_copy     = (const float*)d_in[19];
    const float* b_copy     = (const float*)d_in[20];

    float* out = (float*)d_out;
    float* outputs   = out;
    float* attn_base = out + (size_t)BATCH * TT * VOC;

    fp16 *ench, *encl, *efh, *efl, *wcomb, *we, *wapc, *woc, *wi;
    fp16 *hh0, *hl0, *hh1, *hl1, *ahh, *ahl;
    float *encproj, *ctxwp, *encw, *embproj, *bcomb, *boc, *cst;
    float *q, *ahp2a, *logits_all, *ctxdot;
    SYM(ench, g_ench); SYM(encl, g_encl);
    SYM(efh, g_efh);   SYM(efl, g_efl);
    SYM(encproj, g_encproj); SYM(ctxwp, g_ctxw); SYM(encw, g_encw);
    SYM(embproj, g_embproj);
    SYM(wcomb, g_wcomb); SYM(bcomb, g_bcomb);
    SYM(we, g_we);     SYM(wapc, g_wapc);
    SYM(woc, g_woc);   SYM(boc, g_boc);
    SYM(wi, g_wi);
    SYM(hh0, g_hh0);   SYM(hl0, g_hl0);
    SYM(hh1, g_hh1);   SYM(hl1, g_hl1);
    SYM(cst, g_c);     SYM(q, g_q); SYM(ahp2a, g_ahp2a);
    SYM(ahh, g_ahh_all); SYM(ahl, g_ahl_all);
    SYM(logits_all, g_logits_all); SYM(ctxdot, g_ctxdot);

    fp16* hbh[2] = {hh0, hh1};
    fp16* hbl[2] = {hl0, hl1};

    cudaFuncSetAttribute(mma_gemm_k<128, false>,
                         cudaFuncAttributeMaxDynamicSharedMemorySize, SM128);
    cudaFuncSetAttribute(mma_gemm_k<64, true>,
                         cudaFuncAttributeMaxDynamicSharedMemorySize, SM64);
    cudaFuncSetAttribute(comb_cell_k,
                         cudaFuncAttributeMaxDynamicSharedMemorySize, SM128);
    cudaFuncSetAttribute(ctx_batch_k,
                         cudaFuncAttributeMaxDynamicSharedMemorySize, CTXB_SMEM);

    // ---- prep ----
    split_arr_k<<<4096, 256>>>(enc, ench, encl, (size_t)BATCH * SEQ * HE);
    split_arr_k<<<2048, 256>>>(enc_final, efh, efl, (size_t)BATCH * HE);
    embproj_k<<<dim3(16, VOC), 128>>>(embed, W_ih, b_ih, b_hh, embproj);
    prep_comb_k<<<2048, 256>>>(W_hh, W_dec_attn, W_ap, b_attn, wcomb, bcomb);
    transpose_h_k<<<1024, 256>>>(W_enc_attn, we, HE, HD);
    prep_wapc_k<<<1024, 256>>>(W_ap, wapc);
    prep_outw_k<<<256, 256>>>(W_out, b_out, w_copy, b_copy, woc, boc);
    conv_h_k<<<1024, 256>>>(W_init, wi, (size_t)HD * HE);
    encw_k<<<BATCH * SEQ, 128>>>(enc, w_copy, encw);
    zero_c_k<<<(BATCH * HD + 255) / 256, 256>>>(cst);

    // h^{-1} = enc_final @ W_init^T + b_init
    mma_gemm_k<64, true><<<dim3(8, 32), 256, SM64>>>(
        efh, efl, HE, wi, HE, b_init,
        nullptr, hh0, hl0, HE, HD);
    // enc_proj = enc @ W_enc_attn ; ctxw = enc @ W_ap[:,512:]^T
    mma_gemm_k<128, false><<<dim3(4, 768), 256, SM128>>>(
        ench, encl, HE, we, HE, nullptr,
        encproj, nullptr, nullptr, HE, HD);
    mma_gemm_k<128, false><<<dim3(4, 768), 256, SM128>>>(
        ench, encl, HE, wapc, HE, nullptr,
        ctxwp, nullptr, nullptr, HE, HD);

    // prologue: gates^0 from h^{-1} -> h^0 in buf1
    comb_cell_k<<<dim3(16, 32), 256, SM128>>>(
        hh0, hl0, wcomb, embproj, tgt, bcomb,
        cst, hh1, hl1, q, ahp2a, /*tok_step=*/0, /*noff=*/0);

    for (int t = 0; t < TT; t++) {
        int cur = (t + 1) & 1;   // h^t
        int nxt = t & 1;
        float* ahp2_t = ahp2a + (size_t)t * BATCH * HD;
        if (t < TT - 1) {
            comb_cell_k<<<dim3(24, 32), 256, SM128>>>(
                hbh[cur], hbl[cur], wcomb, embproj, tgt, bcomb,
                cst, hbh[nxt], hbl[nxt], q, ahp2_t, t + 1, 0);
        } else {
            comb_cell_k<<<dim3(8, 32), 256, SM128>>>(
                hbh[cur], hbl[cur], wcomb, embproj, tgt, bcomb,
                cst, nullptr, nullptr, q, ahp2_t, 0, 16);
        }
        attn_score_k<<<BATCH, 128>>>(encproj, q, v_attn, attn_base, t);
    }

    // deferred: batched ctx contraction + ah finalize + ctxdot
    ctx_batch_k<<<BATCH, 256, CTXB_SMEM>>>(
        ctxwp, encw, attn_base, ahp2a, b_ap, ahh, ahl, ctxdot);

    // deferred logits+copy GEMM: M = T*B, N = 121, K = 512
    mma_gemm_k<128, false><<<dim3(1, (TT * BATCH) / 128), 256, SM128>>>(
        ahh, ahl, HD, woc, HD, boc,
        logits_all, nullptr, nullptr, HD, 121);
    out2_k<<<TT * BATCH / 4, 128>>>(logits_all, ctxdot, input_ids, attn_base, outputs);
}

// round 9
// speedup vs baseline: 2.3380x; 1.1450x over previous
#include <cuda_runtime.h>
#include <cuda_fp16.h>
#include <cstdint>

#define BATCH 4096
#define SEQ   24
#define TT    32
#define VOC   120
#define EMB   128
#define HE    512
#define HD    512
#define START_TOKEN 2
#define NG    2048   // interleaved gates

typedef __half fp16;
typedef unsigned int u32;

// ---------------- device scratch ----------------
__device__ __align__(256) fp16 g_ench[(size_t)BATCH * SEQ * HE];
__device__ __align__(256) fp16 g_encl[(size_t)BATCH * SEQ * HE];
__device__ __align__(256) fp16 g_efh[(size_t)BATCH * HE];
__device__ __align__(256) fp16 g_efl[(size_t)BATCH * HE];
__device__ __align__(256) float g_encproj[(size_t)BATCH * SEQ * HD];
__device__ __align__(256) float g_ctxw[(size_t)BATCH * SEQ * HD];
__device__ __align__(256) float g_encw[(size_t)BATCH * SEQ];
__device__ __align__(256) float g_embproj[(size_t)VOC * 4 * HD];   // [tok][4d+g]
// weights (single fp16)
__device__ __align__(256) fp16 g_wg[(size_t)NG * HD];              // W_hh interleaved
__device__ __align__(256) fp16 g_wqa[(size_t)1024 * HD];           // [W_dec^T ; W_ap1]
__device__ __align__(256) float g_bqa[1024];
__device__ __align__(256) fp16 g_we[(size_t)HE * HD];
__device__ __align__(256) fp16 g_wapc[(size_t)HD * HE];
__device__ __align__(256) fp16 g_woc[(size_t)121 * HD];
__device__ __align__(256) float g_boc[121];
__device__ __align__(256) fp16 g_wi[(size_t)HD * HE];
// activations
__device__ __align__(256) fp16 g_hh_all[(size_t)(TT + 1) * BATCH * HD];
__device__ __align__(256) fp16 g_hl_all[(size_t)(TT + 1) * BATCH * HD];
__device__ __align__(256) float g_c[(size_t)BATCH * HD];
__device__ __align__(256) float g_qa[(size_t)TT * BATCH * 1024];   // [q | ahp2]
__device__ __align__(256) fp16 g_ahh_all[(size_t)TT * BATCH * HD];
__device__ __align__(256) fp16 g_ahl_all[(size_t)TT * BATCH * HD];
__device__ __align__(256) float g_logits_all[(size_t)TT * BATCH * 121];
__device__ __align__(256) float g_ctxdot[(size_t)TT * BATCH];

// ---------------- math helpers ----------------
__device__ __forceinline__ float tanh_fast(float x) {
    float e = __expf(2.0f * x);
    return 1.0f - __fdividef(2.0f, e + 1.0f);
}
__device__ __forceinline__ float sigmoid_fast(float x) {
    return __fdividef(1.0f, 1.0f + __expf(-x));
}
__device__ __forceinline__ void split2h(float v, fp16* hi, fp16* lo) {
    fp16 h = __float2half(v);
    *hi = h;
    *lo = __float2half(v - __half2float(h));
}

// ---------------- PTX helpers ----------------
__device__ __forceinline__ u32 smem_u32(const void* p) {
    u32 a;
    asm("{ .reg .u64 t; cvta.to.shared.u64 t, %1; cvt.u32.u64 %0, t; }"
        : "=r"(a) : "l"(p));
    return a;
}
__device__ __forceinline__ void cp16(u32 d, const void* s, u32 sz) {
    asm volatile("cp.async.cg.shared.global [%0], [%1], 16, %2;"
                 :: "r"(d), "l"(s), "r"(sz) : "memory");
}
__device__ __forceinline__ void cp_commit() {
    asm volatile("cp.async.commit_group;" ::: "memory");
}
template<int N>
__device__ __forceinline__ void cp_wait() {
    asm volatile("cp.async.wait_group %0;" :: "n"(N) : "memory");
}
__device__ __forceinline__ void ldsm_x4(u32* r, u32 a) {
    asm volatile("ldmatrix.sync.aligned.m8n8.x4.shared.b16 {%0,%1,%2,%3}, [%4];"
                 : "=r"(r[0]), "=r"(r[1]), "=r"(r[2]), "=r"(r[3]) : "r"(a));
}
__device__ __forceinline__ void mma_f16(float* c, const u32* a, const u32* b) {
    asm volatile(
        "mma.sync.aligned.m16n8k16.row.col.f32.f16.f16.f32 "
        "{%0,%1,%2,%3}, {%4,%5,%6,%7}, {%8,%9}, {%0,%1,%2,%3};"
        : "+f"(c[0]), "+f"(c[1]), "+f"(c[2]), "+f"(c[3])
        : "r"(a[0]), "r"(a[1]), "r"(a[2]), "r"(a[3]), "r"(b[0]), "r"(b[1]));
}

// ======== GEMM mainloop: A fp16 hi/lo pair, B single fp16 ========
#define GEMM_MAINLOOP(BN, NTN, LDA, LDB, NREAL)                                 \
    constexpr int BUFB = 20480 + (BN) * 80;                                     \
    extern __shared__ char smem[];                                              \
    const u32 sb = smem_u32(smem);                                              \
    const int tid = threadIdx.x, lane = tid & 31, wid = tid >> 5;               \
    const int bm = blockIdx.y * 128, bn = blockIdx.x * (BN);                    \
    const int wm = (wid >> 1) * 32, wn = (wid & 1) * ((BN) / 2);                \
    float acc[2][NTN][4];                                                       \
    _Pragma("unroll") for (int m = 0; m < 2; m++)                               \
    _Pragma("unroll") for (int n = 0; n < NTN; n++)                             \
    _Pragma("unroll") for (int j = 0; j < 4; j++) acc[m][n][j] = 0.0f;          \
    const int nch = K / 32;                                                     \
    auto stage = [&](int c) {                                                   \
        const int kt = c * 32;                                                  \
        const u32 bufb = sb + (u32)(c & 1) * BUFB;                              \
        _Pragma("unroll") for (int p = 0; p < 2; p++) {                         \
            int v = tid + p * 256, row = v >> 2, g = v & 3;                     \
            size_t go = (size_t)(bm + row) * (LDA) + kt + g * 8;                \
            u32 sa = bufb + row * 80 + g * 16;                                  \
            cp16(sa, Ah_ + go, 16);                                             \
            cp16(sa + 10240, Al_ + go, 16);                                     \
        }                                                                       \
        _Pragma("unroll") for (int p = 0; p < (BN) / 64; p++) {                 \
            int v = tid + p * 256, row = v >> 2, g = v & 3;                     \
            int n = bn + row;                                                   \
            int na = (n < (NREAL)) ? n : ((NREAL) - 1);                         \
            u32 sz = (n < (NREAL)) ? 16u : 0u;                                  \
            size_t go = (size_t)na * (LDB) + kt + g * 8;                        \
            u32 sa = bufb + 20480 + row * 80 + g * 16;                          \
            cp16(sa, Bw + go, sz);                                              \
        }                                                                       \
    };                                                                          \
    stage(0);                                                                   \
    cp_commit();                                                                \
    for (int c = 0; c < nch; c++) {                                             \
        if (c + 1 < nch) { stage(c + 1); cp_commit(); cp_wait<1>(); }           \
        else             { cp_wait<0>(); }                                      \
        __syncthreads();                                                        \
        const u32 bufb = sb + (u32)(c & 1) * BUFB;                              \
        _Pragma("unroll") for (int k2 = 0; k2 < 2; k2++) {                      \
            const u32 kb = k2 * 32;                                             \
            const u32 a0 = bufb + (wm + (lane & 15)) * 80 + kb + (lane >> 4) * 16; \
            const u32 a1 = a0 + 16 * 80;                                        \
            u32 ahf[2][4], alf[2][4];                                           \
            ldsm_x4(ahf[0], a0); ldsm_x4(ahf[1], a1);                           \
            ldsm_x4(alf[0], a0 + 10240); ldsm_x4(alf[1], a1 + 10240);           \
            const u32 bb0 = bufb + 20480 +                                      \
                (wn + (lane & 7) + ((lane >> 4) & 1) * 8) * 80 +                \
                kb + ((lane >> 3) & 1) * 16;                                    \
            _Pragma("unroll") for (int nt2 = 0; nt2 < (NTN) / 2; nt2++) {       \
                u32 ba = bb0 + nt2 * 16 * 80;                                   \
                u32 bh4[4];                                                     \
                ldsm_x4(bh4, ba);                                               \
                _Pragma("unroll") for (int half = 0; half < 2; half++) {        \
                    int nt = nt2 * 2 + half;                                    \
                    const u32* bhf = bh4 + half * 2;                            \
                    _Pragma("unroll") for (int m = 0; m < 2; m++) {             \
                        mma_f16(acc[m][nt], ahf[m], bhf);                       \
                        mma_f16(acc[m][nt], alf[m], bhf);                       \
                    }                                                           \
                }                                                               \
            }                                                                   \
        }                                                                       \
        __syncthreads();                                                        \
    }

// ---------------- generic GEMM ----------------
template<int BN, bool SPLITOUT>
__global__ __launch_bounds__(256, 2)
void mma_gemm_k(const fp16* __restrict__ Ah_, const fp16* __restrict__ Al_,
                int lda,
                const fp16* __restrict__ Bw, int ldb,
                const float* __restrict__ bias,
                float* __restrict__ C, fp16* __restrict__ Ch, fp16* __restrict__ Cl,
                int K, int Nreal)
{
    GEMM_MAINLOOP(BN, BN / 16, lda, ldb, Nreal)

    auto emit = [&](int r, int n, float v) {
        if (n >= Nreal) return;
        size_t o = (size_t)r * Nreal + n;
        if (bias) v += bias[n];
        if (C) C[o] = v;
        if (SPLITOUT) split2h(v, &Ch[o], &Cl[o]);
    };
#pragma unroll
    for (int m = 0; m < 2; m++) {
        int r0 = bm + wm + m * 16 + (lane >> 2);
#pragma unroll
        for (int nt = 0; nt < BN / 16; nt++) {
            int gn = bn + wn + nt * 8 + (lane & 3) * 2;
            emit(r0,     gn,     acc[m][nt][0]);
            emit(r0,     gn + 1, acc[m][nt][1]);
            emit(r0 + 8, gn,     acc[m][nt][2]);
            emit(r0 + 8, gn + 1, acc[m][nt][3]);
        }
    }
}

// ---------------- fused recurrent gates GEMM + LSTM cell ----------------
// N = 2048 interleaved gates (4d+g, order i,f,g,o); grid (16, 32).
__global__ __launch_bounds__(256, 2)
void comb_cell_k(const fp16* __restrict__ Ah_, const fp16* __restrict__ Al_,
                 const fp16* __restrict__ Bw,
                 const float* __restrict__ ep,     // [VOC][2048]
                 const int* __restrict__ tgt,
                 float* __restrict__ cst,
                 fp16* __restrict__ houth, fp16* __restrict__ houtl,
                 int tok_step)
{
    const int K = HD;
    GEMM_MAINLOOP(128, 8, HD, HD, NG)

#pragma unroll
    for (int m = 0; m < 2; m++) {
        int r0 = bm + wm + m * 16 + (lane >> 2);
        int r1 = r0 + 8;
        int tok0 = (tok_step == 0) ? START_TOKEN : tgt[(size_t)r0 * TT + tok_step - 1];
        int tok1 = (tok_step == 0) ? START_TOKEN : tgt[(size_t)r1 * TT + tok_step - 1];
        const float* e0 = ep + (size_t)tok0 * 4 * HD;
        const float* e1 = ep + (size_t)tok1 * 4 * HD;
#pragma unroll
        for (int nt = 0; nt < 8; nt++) {
            int gn = bn + wn + nt * 8 + (lane & 3) * 2;
            float v0 = acc[m][nt][0] + e0[gn];
            float v1 = acc[m][nt][1] + e0[gn + 1];
            float v2 = acc[m][nt][2] + e1[gn];
            float v3 = acc[m][nt][3] + e1[gn + 1];
            float p0 = __shfl_xor_sync(0xffffffffu, v0, 1);
            float p1 = __shfl_xor_sync(0xffffffffu, v1, 1);
            float p2 = __shfl_xor_sync(0xffffffffu, v2, 1);
            float p3 = __shfl_xor_sync(0xffffffffu, v3, 1);
            if (!(lane & 1)) {
                int d = gn >> 2;
                {
                    size_t ci = (size_t)r0 * HD + d;
                    float cn = sigmoid_fast(v1) * cst[ci]
                             + sigmoid_fast(v0) * tanh_fast(p0);
                    cst[ci] = cn;
                    float hn = sigmoid_fast(p1) * tanh_fast(cn);
                    split2h(hn, &houth[ci], &houtl[ci]);
                }
                {
                    size_t ci = (size_t)r1 * HD + d;
                    float cn = sigmoid_fast(v3) * cst[ci]
                             + sigmoid_fast(v2) * tanh_fast(p2);
                    cst[ci] = cn;
                    float hn = sigmoid_fast(p3) * tanh_fast(cn);
                    split2h(hn, &houth[ci], &houtl[ci]);
                }
            }
        }
    }
}

// ---------------- prep kernels ----------------
__global__ void split_arr_k(const float* __restrict__ src,
                            fp16* __restrict__ h, fp16* __restrict__ l, size_t n)
{
    for (size_t i = (size_t)blockIdx.x * blockDim.x + threadIdx.x; i < n;
         i += (size_t)gridDim.x * blockDim.x)
        split2h(src[i], &h[i], &l[i]);
}

__global__ void transpose_h_k(const float* __restrict__ src,  // [K][N]
                              fp16* __restrict__ w, int Kd, int Nd)
{
    size_t n = (size_t)Kd * Nd;
    for (size_t i = (size_t)blockIdx.x * blockDim.x + threadIdx.x; i < n;
         i += (size_t)gridDim.x * blockDim.x) {
        int k = (int)(i / Nd), nn = (int)(i % Nd);
        w[(size_t)nn * Kd + k] = __float2half(src[i]);
    }
}

// gates weight: n<2048 interleaved (src W_hh row (n&3)*512+(n>>2))
__global__ void prep_wg_k(const float* __restrict__ W_hh, fp16* __restrict__ w)
{
    size_t n = (size_t)NG * HD;
    for (size_t i = (size_t)blockIdx.x * blockDim.x + threadIdx.x; i < n;
         i += (size_t)gridDim.x * blockDim.x) {
        int row = (int)(i / HD), k = (int)(i % HD);
        int src = (row & 3) * HD + (row >> 2);
        w[i] = __float2half(W_hh[(size_t)src * HD + k]);
    }
}

// qa weight: rows 0..511 = W_dec^T; rows 512..1023 = W_ap[r-512][0:512]
__global__ void prep_wqa_k(const float* __restrict__ W_dec,
                           const float* __restrict__ W_ap,
                           const float* __restrict__ b_attn,
                           fp16* __restrict__ w, float* __restrict__ bq)
{
    size_t n = (size_t)1024 * HD;
    for (size_t i = (size_t)blockIdx.x * blockDim.x + threadIdx.x; i < n;
         i += (size_t)gridDim.x * blockDim.x) {
        int row = (int)(i / HD), k = (int)(i % HD);
        float v = (row < 512) ? W_dec[(size_t)k * HD + row]
                              : W_ap[(size_t)(row - 512) * (HD + HE) + k];
        w[i] = __float2half(v);
        if (i < 1024) bq[i] = (i < 512) ? b_attn[i] : 0.0f;
    }
}

__global__ void embproj_k(const float* __restrict__ embed,
                          const float* __restrict__ W_ih,
                          const float* __restrict__ b_ih,
                          const float* __restrict__ b_hh,
                          float* __restrict__ ep)
{
    int v = blockIdx.y;
    int n = blockIdx.x * 128 + threadIdx.x;
    int j = (n & 3) * HD + (n >> 2);
    __shared__ float em[EMB];
    if (threadIdx.x < EMB) em[threadIdx.x] = embed[(size_t)v * EMB + threadIdx.x];
    __syncthreads();
    float acc = b_ih[j] + b_hh[j];
    const float* w = W_ih + (size_t)j * EMB;
#pragma unroll 8
    for (int k = 0; k < EMB; k++) acc += em[k] * w[k];
    ep[(size_t)v * 4 * HD + n] = acc;
}

__global__ void prep_outw_k(const float* __restrict__ W_out,
                            const float* __restrict__ b_out,
                            const float* __restrict__ w_copy,
                            const float* __restrict__ b_copy,
                            fp16* __restrict__ w, float* __restrict__ bo)
{
    size_t n = (size_t)121 * HD;
    for (size_t i = (size_t)blockIdx.x * blockDim.x + threadIdx.x; i < n;
         i += (size_t)gridDim.x * blockDim.x) {
        int row = (int)(i / HD), k = (int)(i % HD);
        float v = (row < VOC) ? W_out[(size_t)row * HD + k] : w_copy[k];
        w[i] = __float2half(v);
        if (i < 121) bo[i] = (i < VOC) ? b_out[i] : b_copy[0];
    }
}

__global__ void prep_wapc_k(const float* __restrict__ W_ap, fp16* __restrict__ w)
{
    size_t n = (size_t)HD * HE;
    for (size_t i = (size_t)blockIdx.x * blockDim.x + threadIdx.x; i < n;
         i += (size_t)gridDim.x * blockDim.x) {
        int row = (int)(i / HE), k = (int)(i % HE);
        w[i] = __float2half(W_ap[(size_t)row * (HD + HE) + HD + k]);
    }
}

__global__ void conv_h_k(const float* __restrict__ src, fp16* __restrict__ dst, size_t n)
{
    for (size_t i = (size_t)blockIdx.x * blockDim.x + threadIdx.x; i < n;
         i += (size_t)gridDim.x * blockDim.x)
        dst[i] = __float2half(src[i]);
}

__global__ void encw_k(const float* __restrict__ enc,
                       const float* __restrict__ w_copy,
                       float* __restrict__ encw)
{
    int r = blockIdx.x;
    int tid = threadIdx.x;
    __shared__ float red[128];
    const float* row = enc + (size_t)r * HE;
    float acc = 0.f;
    for (int k = tid; k < HE; k += 128) acc += row[k] * w_copy[HD + k];
    red[tid] = acc;
    __syncthreads();
    for (int s2 = 64; s2; s2 >>= 1) {
        if (tid < s2) red[tid] += red[tid + s2];
        __syncthreads();
    }
    if (tid == 0) encw[r] = red[0];
}

__global__ void zero_c_k(float* __restrict__ c)
{
    size_t i = (size_t)blockIdx.x * blockDim.x + threadIdx.x;
    if (i < (size_t)BATCH * HD) c[i] = 0.0f;
}

// ---------------- batched attention: block per b, all T steps ----------------
// smem: ep[SEQ*HD] + q[4*HD] + sc[4*SEQ]
#define ATT_SMEM ((SEQ * HD + 4 * HD + 4 * SEQ) * 4)
__global__ __launch_bounds__(256)
void attn_batch_k(const float* __restrict__ encproj,
                  const float* __restrict__ qa,     // [t*B+b][1024], q at 0..511
                  const float* __restrict__ v_attn,
                  float* __restrict__ attn_out)     // [b][t][s]
{
    int b = blockIdx.x;
    int tid = threadIdx.x;
    extern __shared__ float sm[];
    float* ep = sm;                  // SEQ*HD
    float* qs = sm + SEQ * HD;       // 4*HD
    float* sc = qs + 4 * HD;         // 4*SEQ
    __shared__ __align__(16) float vsh[HD];

    {
        const float4* src = (const float4*)(encproj + (size_t)b * SEQ * HD);
        float4* dst = (float4*)ep;
        for (int i = tid; i < SEQ * HD / 4; i += 256) dst[i] = src[i];
    }
    for (int d = tid; d < HD; d += 256) vsh[d] = v_attn[d];
    __syncthreads();

    int w = tid >> 5, lane = tid & 31;
    for (int tc = 0; tc < TT; tc += 4) {
        // load q for 4 steps
        for (int i = tid; i < 4 * HD / 4; i += 256) {
            int t = i / (HD / 4), dd = i % (HD / 4);
            ((float4*)qs)[i] =
                ((const float4*)(qa + ((size_t)(tc + t) * BATCH + b) * 1024))[dd];
        }
        __syncthreads();

        for (int task = w; task < 4 * SEQ; task += 8) {
            int t = task / SEQ, s = task % SEQ;
            const float4* row4 = (const float4*)(ep + s * HD);
            const float4* q4p = (const float4*)(qs + t * HD);
            float acc = 0.f;
#pragma unroll
            for (int j = 0; j < 4; j++) {
                int d4 = lane + j * 32;
                float4 e4 = row4[d4];
                float4 q4 = q4p[d4];
                float4 v4 = *(const float4*)&vsh[d4 * 4];
                acc += tanh_fast(e4.x + q4.x) * v4.x;
                acc += tanh_fast(e4.y + q4.y) * v4.y;
                acc += tanh_fast(e4.z + q4.z) * v4.z;
                acc += tanh_fast(e4.w + q4.w) * v4.w;
            }
#pragma unroll
            for (int o = 16; o; o >>= 1) acc += __shfl_xor_sync(0xffffffffu, acc, o);
            if (lane == 0) sc[t * SEQ + s] = acc;
        }
        __syncthreads();

        if (w < 4) {
            float e = (lane < SEQ) ? __expf(sc[w * SEQ + lane]) : 0.f;
            float sum = e;
#pragma unroll
            for (int o = 16; o; o >>= 1) sum += __shfl_xor_sync(0xffffffffu, sum, o);
            if (lane < SEQ)
                attn_out[(size_t)b * TT * SEQ + (size_t)(tc + w) * SEQ + lane] =
                    __fdividef(e, sum);
        }
        __syncthreads();
    }
}

// ---------------- deferred batched ctx pass ----------------
#define CTXB_SMEM ((SEQ * HD + TT * SEQ + SEQ) * 4)
__global__ __launch_bounds__(256)
void ctx_batch_k(const float* __restrict__ ctxw,
                 const float* __restrict__ encw,
                 const float* __restrict__ aprob,    // attn_base [b][t][s]
                 const float* __restrict__ qa,       // ahp2 at cols 512..1023
                 const float* __restrict__ b_ap,
                 fp16* __restrict__ ahh, fp16* __restrict__ ahl,
                 float* __restrict__ ctxdot)
{
    int b = blockIdx.x;
    int tid = threadIdx.x;
    extern __shared__ float sm[];
    float* cw = sm;
    float* ap = sm + SEQ * HD;
    float* ew = ap + TT * SEQ;

    {
        const float4* src = (const float4*)(ctxw + (size_t)b * SEQ * HD);
        float4* dst = (float4*)cw;
        for (int i = tid; i < SEQ * HD / 4; i += 256) dst[i] = src[i];
    }
    for (int i = tid; i < TT * SEQ; i += 256)
        ap[i] = aprob[(size_t)b * TT * SEQ + i];
    if (tid < SEQ) ew[tid] = encw[(size_t)b * SEQ + tid];
    __syncthreads();

    if (tid < TT) {
        float cd = 0.f;
#pragma unroll
        for (int s = 0; s < SEQ; s++) cd += ap[tid * SEQ + s] * ew[s];
        ctxdot[(size_t)tid * BATCH + b] = cd;
    }

    float bap0 = b_ap[tid], bap1 = b_ap[tid + 256];
    for (int t = 0; t < TT; t++) {
        float a0 = 0.f, a1 = 0.f;
        const float* apt = ap + t * SEQ;
#pragma unroll
        for (int s = 0; s < SEQ; s++) {
            float a = apt[s];
            a0 += a * cw[s * HD + tid];
            a1 += a * cw[s * HD + tid + 256];
        }
        const float* qrow = qa + ((size_t)t * BATCH + b) * 1024 + 512;
        size_t base = (size_t)t * BATCH * HD + (size_t)b * HD;
        float v0 = tanh_fast(qrow[tid] + a0 + bap0);
        float v1 = tanh_fast(qrow[tid + 256] + a1 + bap1);
        split2h(v0, &ahh[base + tid],       &ahl[base + tid]);
        split2h(v1, &ahh[base + tid + 256], &ahl[base + tid + 256]);
    }
}

// ---------------- output mix: warp per (t,b) row ----------------
__global__ void out2_k(const float* __restrict__ logits_all,
                       const float* __restrict__ ctxdot,
                       const int* __restrict__ input_char_ids,
                       const float* __restrict__ attn_base,
                       float* __restrict__ outputs)
{
    int warp = threadIdx.x >> 5, lane = threadIdx.x & 31;
    int row = blockIdx.x * 4 + warp;
    int t = row >> 12;
    int b = row & 4095;
    __shared__ float cbuf[4][VOC];

    for (int k = lane; k < VOC; k += 32) cbuf[warp][k] = 0.f;
    __syncwarp();
    if (lane < SEQ) {
        int id = input_char_ids[(size_t)b * SEQ + lane];
        float a = attn_base[(size_t)b * TT * SEQ + (size_t)t * SEQ + lane];
        atomicAdd(&cbuf[warp][id], a);
    }
    __syncwarp();

    const float* lrow = logits_all + (size_t)row * 121;
    float p = sigmoid_fast(lrow[120] + ctxdot[row]);

    float e[4];
    float sum = 0.f;
#pragma unroll
    for (int j = 0; j < 4; j++) {
        int idx = lane + j * 32;
        e[j] = (idx < VOC) ? __expf(lrow[idx]) : 0.f;
        sum += e[j];
    }
#pragma unroll
    for (int o = 16; o; o >>= 1) sum += __shfl_xor_sync(0xffffffffu, sum, o);
    float inv = __fdividef(1.0f - p, sum);
#pragma unroll
    for (int j = 0; j < 4; j++) {
        int idx = lane + j * 32;
        if (idx < VOC)
            outputs[(size_t)b * TT * VOC + (size_t)t * VOC + idx] =
                inv * e[j] + p * cbuf[warp][idx];
    }
}

// ---------------- host ----------------
#define SYM(p, s) cudaGetSymbolAddress((void**)&(p), s)
#define SM128 61440
#define SM64  51200

extern "C" void kernel_launch(void* const* d_in, const int* in_sizes, int n_in,
                              void* d_out, int out_size)
{
    (void)in_sizes; (void)n_in; (void)out_size;
    const float* enc        = (const float*)d_in[0];
    const float* enc_final  = (const float*)d_in[1];
    const int*   tgt        = (const int*)d_in[2];
    const int*   input_ids  = (const int*)d_in[3];
    const float* embed      = (const float*)d_in[4];
    const float* W_init     = (const float*)d_in[5];
    const float* b_init     = (const float*)d_in[6];
    const float* W_ih       = (const float*)d_in[7];
    const float* W_hh       = (const float*)d_in[8];
    const float* b_ih       = (const float*)d_in[9];
    const float* b_hh       = (const float*)d_in[10];
    const float* W_enc_attn = (const float*)d_in[11];
    const float* W_dec_attn = (const float*)d_in[12];
    const float* b_attn     = (const float*)d_in[13];
    const float* v_attn     = (const float*)d_in[14];
    const float* W_ap       = (const float*)d_in[15];
    const float* b_ap       = (const float*)d_in[16];
    const float* W_out      = (const float*)d_in[17];
    const float* b_out      = (const float*)d_in[18];
    const float* w_copy     = (const float*)d_in[19];
    const float* b_copy     = (const float*)d_in[20];

    float* out = (float*)d_out;
    float* outputs   = out;
    float* attn_base = out + (size_t)BATCH * TT * VOC;

    fp16 *ench, *encl, *efh, *efl, *wg, *wqa, *we, *wapc, *woc, *wi;
    fp16 *hh_all, *hl_all, *ahh, *ahl;
    float *encproj, *ctxwp, *encw, *embproj, *bqa, *boc, *cst;
    float *qa, *logits_all, *ctxdot;
    SYM(ench, g_ench); SYM(encl, g_encl);
    SYM(efh, g_efh);   SYM(efl, g_efl);
    SYM(encproj, g_encproj); SYM(ctxwp, g_ctxw); SYM(encw, g_encw);
    SYM(embproj, g_embproj);
    SYM(wg, g_wg);     SYM(wqa, g_wqa); SYM(bqa, g_bqa);
    SYM(we, g_we);     SYM(wapc, g_wapc);
    SYM(woc, g_woc);   SYM(boc, g_boc);
    SYM(wi, g_wi);
    SYM(hh_all, g_hh_all); SYM(hl_all, g_hl_all);
    SYM(cst, g_c);     SYM(qa, g_qa);
    SYM(ahh, g_ahh_all); SYM(ahl, g_ahl_all);
    SYM(logits_all, g_logits_all); SYM(ctxdot, g_ctxdot);

    cudaFuncSetAttribute(mma_gemm_k<128, false>,
                         cudaFuncAttributeMaxDynamicSharedMemorySize, SM128);
    cudaFuncSetAttribute(mma_gemm_k<64, true>,
                         cudaFuncAttributeMaxDynamicSharedMemorySize, SM64);
    cudaFuncSetAttribute(comb_cell_k,
                         cudaFuncAttributeMaxDynamicSharedMemorySize, SM128);
    cudaFuncSetAttribute(attn_batch_k,
                         cudaFuncAttributeMaxDynamicSharedMemorySize, ATT_SMEM);
    cudaFuncSetAttribute(ctx_batch_k,
                         cudaFuncAttributeMaxDynamicSharedMemorySize, CTXB_SMEM);

    // ---- prep ----
    split_arr_k<<<4096, 256>>>(enc, ench, encl, (size_t)BATCH * SEQ * HE);
    split_arr_k<<<2048, 256>>>(enc_final, efh, efl, (size_t)BATCH * HE);
    embproj_k<<<dim3(16, VOC), 128>>>(embed, W_ih, b_ih, b_hh, embproj);
    prep_wg_k<<<1024, 256>>>(W_hh, wg);
    prep_wqa_k<<<1024, 256>>>(W_dec_attn, W_ap, b_attn, wqa, bqa);
    transpose_h_k<<<1024, 256>>>(W_enc_attn, we, HE, HD);
    prep_wapc_k<<<1024, 256>>>(W_ap, wapc);
    prep_outw_k<<<256, 256>>>(W_out, b_out, w_copy, b_copy, woc, boc);
    conv_h_k<<<1024, 256>>>(W_init, wi, (size_t)HD * HE);
    encw_k<<<BATCH * SEQ, 128>>>(enc, w_copy, encw);
    zero_c_k<<<(BATCH * HD + 255) / 256, 256>>>(cst);

    // h_all[0] = enc_final @ W_init^T + b_init
    mma_gemm_k<64, true><<<dim3(8, 32), 256, SM64>>>(
        efh, efl, HE, wi, HE, b_init,
        nullptr, hh_all, hl_all, HE, HD);
    // enc_proj = enc @ W_enc_attn ; ctxw = enc @ W_ap[:,512:]^T
    mma_gemm_k<128, false><<<dim3(4, 768), 256, SM128>>>(
        ench, encl, HE, we, HE, nullptr,
        encproj, nullptr, nullptr, HE, HD);
    mma_gemm_k<128, false><<<dim3(4, 768), 256, SM128>>>(
        ench, encl, HE, wapc, HE, nullptr,
        ctxwp, nullptr, nullptr, HE, HD);

    // serial recurrence: ONLY the gates GEMM + cell per step
    for (int t = 0; t < TT; t++) {
        size_t off = (size_t)t * BATCH * HD;
        comb_cell_k<<<dim3(16, 32), 256, SM128>>>(
            hh_all + off, hl_all + off, wg, embproj, tgt,
            cst, hh_all + off + (size_t)BATCH * HD,
            hl_all + off + (size_t)BATCH * HD, t);
    }

    // deferred: [q | ahp2] for ALL steps: M = T*B, N = 1024, K = 512
    mma_gemm_k<128, false><<<dim3(8, (TT * BATCH) / 128), 256, SM128>>>(
        hh_all + (size_t)BATCH * HD, hl_all + (size_t)BATCH * HD, HD,
        wqa, HD, bqa,
        qa, nullptr, nullptr, HD, 1024);

    // batched attention over all steps (encproj staged once per b)
    attn_batch_k<<<BATCH, 256, ATT_SMEM>>>(encproj, qa, v_attn, attn_base);

    // batched ctx contraction + ah finalize + ctxdot
    ctx_batch_k<<<BATCH, 256, CTXB_SMEM>>>(
        ctxwp, encw, attn_base, qa, b_ap, ahh, ahl, ctxdot);

    // deferred logits+copy GEMM: M = T*B, N = 121, K = 512
    mma_gemm_k<128, false><<<dim3(1, (TT * BATCH) / 128), 256, SM128>>>(
        ahh, ahl, HD, woc, HD, boc,
        logits_all, nullptr, nullptr, HD, 121);
    out2_k<<<TT * BATCH / 4, 128>>>(logits_all, ctxdot, input_ids, attn_base, outputs);
}

// round 10
// speedup vs baseline: 2.9717x; 1.2710x over previous
#include <cuda_runtime.h>
#include <cuda_fp16.h>
#include <cstdint>

#define BATCH 4096
#define SEQ   24
#define TT    32
#define VOC   120
#define EMB   128
#define HE    512
#define HD    512
#define START_TOKEN 2
#define NG    2048   // interleaved gates

typedef __half fp16;
typedef unsigned int u32;

// ---------------- device scratch ----------------
__device__ __align__(256) fp16 g_ench[(size_t)BATCH * SEQ * HE];
__device__ __align__(256) fp16 g_ef[(size_t)BATCH * HE];
__device__ __align__(256) float g_encproj[(size_t)BATCH * SEQ * HD];
__device__ __align__(256) float g_ctxw[(size_t)BATCH * SEQ * HD];
__device__ __align__(256) float g_encw[(size_t)BATCH * SEQ];
__device__ __align__(256) float g_embproj[(size_t)VOC * 4 * HD];   // [tok][4d+g]
// weights (single fp16)
__device__ __align__(256) fp16 g_wg[(size_t)NG * HD];              // W_hh interleaved
__device__ __align__(256) fp16 g_wqa[(size_t)1024 * HD];           // [W_dec^T ; W_ap1]
__device__ __align__(256) float g_bqa[1024];
__device__ __align__(256) fp16 g_we[(size_t)HE * HD];
__device__ __align__(256) fp16 g_wapc[(size_t)HD * HE];
__device__ __align__(256) fp16 g_woc[(size_t)121 * HD];
__device__ __align__(256) float g_boc[121];
__device__ __align__(256) fp16 g_wi[(size_t)HD * HE];
// activations (single fp16)
__device__ __align__(256) fp16 g_h_all[(size_t)(TT + 1) * BATCH * HD];
__device__ __align__(256) float g_c[(size_t)BATCH * HD];
__device__ __align__(256) float g_qa[(size_t)TT * BATCH * 1024];   // [q | ahp2]
__device__ __align__(256) fp16 g_ah_all[(size_t)TT * BATCH * HD];
__device__ __align__(256) float g_logits_all[(size_t)TT * BATCH * 121];
__device__ __align__(256) float g_ctxdot[(size_t)TT * BATCH];

// ---------------- math helpers ----------------
__device__ __forceinline__ float tanh_fast(float x) {
    float e = __expf(2.0f * x);
    return 1.0f - __fdividef(2.0f, e + 1.0f);
}
__device__ __forceinline__ float sigmoid_fast(float x) {
    return __fdividef(1.0f, 1.0f + __expf(-x));
}

// ---------------- PTX helpers ----------------
__device__ __forceinline__ u32 smem_u32(const void* p) {
    u32 a;
    asm("{ .reg .u64 t; cvta.to.shared.u64 t, %1; cvt.u32.u64 %0, t; }"
        : "=r"(a) : "l"(p));
    return a;
}
__device__ __forceinline__ void cp16(u32 d, const void* s, u32 sz) {
    asm volatile("cp.async.cg.shared.global [%0], [%1], 16, %2;"
                 :: "r"(d), "l"(s), "r"(sz) : "memory");
}
__device__ __forceinline__ void cp_commit() {
    asm volatile("cp.async.commit_group;" ::: "memory");
}
template<int N>
__device__ __forceinline__ void cp_wait() {
    asm volatile("cp.async.wait_group %0;" :: "n"(N) : "memory");
}
__device__ __forceinline__ void ldsm_x4(u32* r, u32 a) {
    asm volatile("ldmatrix.sync.aligned.m8n8.x4.shared.b16 {%0,%1,%2,%3}, [%4];"
                 : "=r"(r[0]), "=r"(r[1]), "=r"(r[2]), "=r"(r[3]) : "r"(a));
}
__device__ __forceinline__ void mma_f16(float* c, const u32* a, const u32* b) {
    asm volatile(
        "mma.sync.aligned.m16n8k16.row.col.f32.f16.f16.f32 "
        "{%0,%1,%2,%3}, {%4,%5,%6,%7}, {%8,%9}, {%0,%1,%2,%3};"
        : "+f"(c[0]), "+f"(c[1]), "+f"(c[2]), "+f"(c[3])
        : "r"(a[0]), "r"(a[1]), "r"(a[2]), "r"(a[3]), "r"(b[0]), "r"(b[1]));
}

// ======== GEMM mainloop: A single fp16, B single fp16 ========
// per-buffer: A@0 (10240 B) B@10240 (BN*80 B); row stride 80 B.
#define GEMM_MAINLOOP(BN, NTN, LDA, LDB, NREAL)                                 \
    constexpr int BUFB = 10240 + (BN) * 80;                                     \
    extern __shared__ char smem[];                                              \
    const u32 sb = smem_u32(smem);                                              \
    const int tid = threadIdx.x, lane = tid & 31, wid = tid >> 5;               \
    const int bm = blockIdx.y * 128, bn = blockIdx.x * (BN);                    \
    const int wm = (wid >> 1) * 32, wn = (wid & 1) * ((BN) / 2);                \
    float acc[2][NTN][4];                                                       \
    _Pragma("unroll") for (int m = 0; m < 2; m++)                               \
    _Pragma("unroll") for (int n = 0; n < NTN; n++)                             \
    _Pragma("unroll") for (int j = 0; j < 4; j++) acc[m][n][j] = 0.0f;          \
    const int nch = K / 32;                                                     \
    auto stage = [&](int c) {                                                   \
        const int kt = c * 32;                                                  \
        const u32 bufb = sb + (u32)(c & 1) * BUFB;                              \
        _Pragma("unroll") for (int p = 0; p < 2; p++) {                         \
            int v = tid + p * 256, row = v >> 2, g = v & 3;                     \
            size_t go = (size_t)(bm + row) * (LDA) + kt + g * 8;                \
            cp16(bufb + row * 80 + g * 16, Aw + go, 16);                        \
        }                                                                       \
        _Pragma("unroll") for (int p = 0; p < (BN) / 64; p++) {                 \
            int v = tid + p * 256, row = v >> 2, g = v & 3;                     \
            int n = bn + row;                                                   \
            int na = (n < (NREAL)) ? n : ((NREAL) - 1);                         \
            u32 sz = (n < (NREAL)) ? 16u : 0u;                                  \
            size_t go = (size_t)na * (LDB) + kt + g * 8;                        \
            cp16(bufb + 10240 + row * 80 + g * 16, Bw + go, sz);                \
        }                                                                       \
    };                                                                          \
    stage(0);                                                                   \
    cp_commit();                                                                \
    for (int c = 0; c < nch; c++) {                                             \
        if (c + 1 < nch) { stage(c + 1); cp_commit(); cp_wait<1>(); }           \
        else             { cp_wait<0>(); }                                      \
        __syncthreads();                                                        \
        const u32 bufb = sb + (u32)(c & 1) * BUFB;                              \
        _Pragma("unroll") for (int k2 = 0; k2 < 2; k2++) {                      \
            const u32 kb = k2 * 32;                                             \
            const u32 a0 = bufb + (wm + (lane & 15)) * 80 + kb + (lane >> 4) * 16; \
            u32 ahf[2][4];                                                      \
            ldsm_x4(ahf[0], a0); ldsm_x4(ahf[1], a0 + 16 * 80);                 \
            const u32 bb0 = bufb + 10240 +                                      \
                (wn + (lane & 7) + ((lane >> 4) & 1) * 8) * 80 +                \
                kb + ((lane >> 3) & 1) * 16;                                    \
            _Pragma("unroll") for (int nt2 = 0; nt2 < (NTN) / 2; nt2++) {       \
                u32 bh4[4];                                                     \
                ldsm_x4(bh4, bb0 + nt2 * 16 * 80);                              \
                _Pragma("unroll") for (int half = 0; half < 2; half++) {        \
                    int nt = nt2 * 2 + half;                                    \
                    const u32* bhf = bh4 + half * 2;                            \
                    _Pragma("unroll") for (int m = 0; m < 2; m++)               \
                        mma_f16(acc[m][nt], ahf[m], bhf);                       \
                }                                                               \
            }                                                                   \
        }                                                                       \
        __syncthreads();                                                        \
    }

// ---------------- generic GEMM ----------------
template<int BN, bool HALFOUT>
__global__ __launch_bounds__(256, 2)
void mma_gemm_k(const fp16* __restrict__ Aw, int lda,
                const fp16* __restrict__ Bw, int ldb,
                const float* __restrict__ bias,
                float* __restrict__ C, fp16* __restrict__ Ch,
                int K, int Nreal)
{
    GEMM_MAINLOOP(BN, BN / 16, lda, ldb, Nreal)

    auto emit = [&](int r, int n, float v) {
        if (n >= Nreal) return;
        size_t o = (size_t)r * Nreal + n;
        if (bias) v += bias[n];
        if (C) C[o] = v;
        if (HALFOUT) Ch[o] = __float2half(v);
    };
#pragma unroll
    for (int m = 0; m < 2; m++) {
        int r0 = bm + wm + m * 16 + (lane >> 2);
#pragma unroll
        for (int nt = 0; nt < BN / 16; nt++) {
            int gn = bn + wn + nt * 8 + (lane & 3) * 2;
            emit(r0,     gn,     acc[m][nt][0]);
            emit(r0,     gn + 1, acc[m][nt][1]);
            emit(r0 + 8, gn,     acc[m][nt][2]);
            emit(r0 + 8, gn + 1, acc[m][nt][3]);
        }
    }
}

// ---------------- fused recurrent gates GEMM + LSTM cell ----------------
// N = 2048 interleaved gates (4d+g, order i,f,g,o); grid (16, 32).
__global__ __launch_bounds__(256, 2)
void comb_cell_k(const fp16* __restrict__ Aw,
                 const fp16* __restrict__ Bw,
                 const float* __restrict__ ep,     // [VOC][2048]
                 const int* __restrict__ tgt,
                 float* __restrict__ cst,
                 fp16* __restrict__ hout,
                 int tok_step)
{
    const int K = HD;
    GEMM_MAINLOOP(128, 8, HD, HD, NG)

#pragma unroll
    for (int m = 0; m < 2; m++) {
        int r0 = bm + wm + m * 16 + (lane >> 2);
        int r1 = r0 + 8;
        int tok0 = (tok_step == 0) ? START_TOKEN : tgt[(size_t)r0 * TT + tok_step - 1];
        int tok1 = (tok_step == 0) ? START_TOKEN : tgt[(size_t)r1 * TT + tok_step - 1];
        const float* e0 = ep + (size_t)tok0 * 4 * HD;
        const float* e1 = ep + (size_t)tok1 * 4 * HD;
#pragma unroll
        for (int nt = 0; nt < 8; nt++) {
            int gn = bn + wn + nt * 8 + (lane & 3) * 2;
            float v0 = acc[m][nt][0] + e0[gn];
            float v1 = acc[m][nt][1] + e0[gn + 1];
            float v2 = acc[m][nt][2] + e1[gn];
            float v3 = acc[m][nt][3] + e1[gn + 1];
            float p0 = __shfl_xor_sync(0xffffffffu, v0, 1);
            float p1 = __shfl_xor_sync(0xffffffffu, v1, 1);
            float p2 = __shfl_xor_sync(0xffffffffu, v2, 1);
            float p3 = __shfl_xor_sync(0xffffffffu, v3, 1);
            if (!(lane & 1)) {
                int d = gn >> 2;
                {
                    size_t ci = (size_t)r0 * HD + d;
                    float cn = sigmoid_fast(v1) * cst[ci]
                             + sigmoid_fast(v0) * tanh_fast(p0);
                    cst[ci] = cn;
                    hout[ci] = __float2half(sigmoid_fast(p1) * tanh_fast(cn));
                }
                {
                    size_t ci = (size_t)r1 * HD + d;
                    float cn = sigmoid_fast(v3) * cst[ci]
                             + sigmoid_fast(v2) * tanh_fast(p2);
                    cst[ci] = cn;
                    hout[ci] = __float2half(sigmoid_fast(p3) * tanh_fast(cn));
                }
            }
        }
    }
}

// ---------------- prep kernels ----------------
__global__ void conv_h_k(const float* __restrict__ src, fp16* __restrict__ dst, size_t n)
{
    for (size_t i = (size_t)blockIdx.x * blockDim.x + threadIdx.x; i < n;
         i += (size_t)gridDim.x * blockDim.x)
        dst[i] = __float2half(src[i]);
}

__global__ void transpose_h_k(const float* __restrict__ src,  // [K][N]
                              fp16* __restrict__ w, int Kd, int Nd)
{
    size_t n = (size_t)Kd * Nd;
    for (size_t i = (size_t)blockIdx.x * blockDim.x + threadIdx.x; i < n;
         i += (size_t)gridDim.x * blockDim.x) {
        int k = (int)(i / Nd), nn = (int)(i % Nd);
        w[(size_t)nn * Kd + k] = __float2half(src[i]);
    }
}

__global__ void prep_wg_k(const float* __restrict__ W_hh, fp16* __restrict__ w)
{
    size_t n = (size_t)NG * HD;
    for (size_t i = (size_t)blockIdx.x * blockDim.x + threadIdx.x; i < n;
         i += (size_t)gridDim.x * blockDim.x) {
        int row = (int)(i / HD), k = (int)(i % HD);
        int src = (row & 3) * HD + (row >> 2);
        w[i] = __float2half(W_hh[(size_t)src * HD + k]);
    }
}

__global__ void prep_wqa_k(const float* __restrict__ W_dec,
                           const float* __restrict__ W_ap,
                           const float* __restrict__ b_attn,
                           fp16* __restrict__ w, float* __restrict__ bq)
{
    size_t n = (size_t)1024 * HD;
    for (size_t i = (size_t)blockIdx.x * blockDim.x + threadIdx.x; i < n;
         i += (size_t)gridDim.x * blockDim.x) {
        int row = (int)(i / HD), k = (int)(i % HD);
        float v = (row < 512) ? W_dec[(size_t)k * HD + row]
                              : W_ap[(size_t)(row - 512) * (HD + HE) + k];
        w[i] = __float2half(v);
        if (i < 1024) bq[i] = (i < 512) ? b_attn[i] : 0.0f;
    }
}

__global__ void embproj_k(const float* __restrict__ embed,
                          const float* __restrict__ W_ih,
                          const float* __restrict__ b_ih,
                          const float* __restrict__ b_hh,
                          float* __restrict__ ep)
{
    int v = blockIdx.y;
    int n = blockIdx.x * 128 + threadIdx.x;
    int j = (n & 3) * HD + (n >> 2);
    __shared__ float em[EMB];
    if (threadIdx.x < EMB) em[threadIdx.x] = embed[(size_t)v * EMB + threadIdx.x];
    __syncthreads();
    float acc = b_ih[j] + b_hh[j];
    const float* w = W_ih + (size_t)j * EMB;
#pragma unroll 8
    for (int k = 0; k < EMB; k++) acc += em[k] * w[k];
    ep[(size_t)v * 4 * HD + n] = acc;
}

__global__ void prep_outw_k(const float* __restrict__ W_out,
                            const float* __restrict__ b_out,
                            const float* __restrict__ w_copy,
                            const float* __restrict__ b_copy,
                            fp16* __restrict__ w, float* __restrict__ bo)
{
    size_t n = (size_t)121 * HD;
    for (size_t i = (size_t)blockIdx.x * blockDim.x + threadIdx.x; i < n;
         i += (size_t)gridDim.x * blockDim.x) {
        int row = (int)(i / HD), k = (int)(i % HD);
        float v = (row < VOC) ? W_out[(size_t)row * HD + k] : w_copy[k];
        w[i] = __float2half(v);
        if (i < 121) bo[i] = (i < VOC) ? b_out[i] : b_copy[0];
    }
}

__global__ void prep_wapc_k(const float* __restrict__ W_ap, fp16* __restrict__ w)
{
    size_t n = (size_t)HD * HE;
    for (size_t i = (size_t)blockIdx.x * blockDim.x + threadIdx.x; i < n;
         i += (size_t)gridDim.x * blockDim.x) {
        int row = (int)(i / HE), k = (int)(i % HE);
        w[i] = __float2half(W_ap[(size_t)row * (HD + HE) + HD + k]);
    }
}

__global__ void encw_k(const float* __restrict__ enc,
                       const float* __restrict__ w_copy,
                       float* __restrict__ encw)
{
    int r = blockIdx.x;
    int tid = threadIdx.x;
    __shared__ float red[128];
    const float* row = enc + (size_t)r * HE;
    float acc = 0.f;
    for (int k = tid; k < HE; k += 128) acc += row[k] * w_copy[HD + k];
    red[tid] = acc;
    __syncthreads();
    for (int s2 = 64; s2; s2 >>= 1) {
        if (tid < s2) red[tid] += red[tid + s2];
        __syncthreads();
    }
    if (tid == 0) encw[r] = red[0];
}

__global__ void zero_c_k(float* __restrict__ c)
{
    size_t i = (size_t)blockIdx.x * blockDim.x + threadIdx.x;
    if (i < (size_t)BATCH * HD) c[i] = 0.0f;
}

// ---------------- batched attention: block per b, all T steps ----------------
#define ATT_SMEM ((SEQ * HD + 4 * HD + 4 * SEQ) * 4)
__global__ __launch_bounds__(256)
void attn_batch_k(const float* __restrict__ encproj,
                  const float* __restrict__ qa,     // [t*B+b][1024], q at 0..511
                  const float* __restrict__ v_attn,
                  float* __restrict__ attn_out)     // [b][t][s]
{
    int b = blockIdx.x;
    int tid = threadIdx.x;
    extern __shared__ float sm[];
    float* ep = sm;                  // SEQ*HD
    float* qs = sm + SEQ * HD;       // 4*HD
    float* sc = qs + 4 * HD;         // 4*SEQ
    __shared__ __align__(16) float vsh[HD];

    {
        const float4* src = (const float4*)(encproj + (size_t)b * SEQ * HD);
        float4* dst = (float4*)ep;
        for (int i = tid; i < SEQ * HD / 4; i += 256) dst[i] = src[i];
    }
    for (int d = tid; d < HD; d += 256) vsh[d] = v_attn[d];
    __syncthreads();

    int w = tid >> 5, lane = tid & 31;
    for (int tc = 0; tc < TT; tc += 4) {
        for (int i = tid; i < 4 * HD / 4; i += 256) {
            int t = i / (HD / 4), dd = i % (HD / 4);
            ((float4*)qs)[i] =
                ((const float4*)(qa + ((size_t)(tc + t) * BATCH + b) * 1024))[dd];
        }
        __syncthreads();

        for (int task = w; task < 4 * SEQ; task += 8) {
            int t = task / SEQ, s = task % SEQ;
            const float4* row4 = (const float4*)(ep + s * HD);
            const float4* q4p = (const float4*)(qs + t * HD);
            float acc = 0.f;
#pragma unroll
            for (int j = 0; j < 4; j++) {
                int d4 = lane + j * 32;
                float4 e4 = row4[d4];
                float4 q4 = q4p[d4];
                float4 v4 = *(const float4*)&vsh[d4 * 4];
                acc += tanh_fast(e4.x + q4.x) * v4.x;
                acc += tanh_fast(e4.y + q4.y) * v4.y;
                acc += tanh_fast(e4.z + q4.z) * v4.z;
                acc += tanh_fast(e4.w + q4.w) * v4.w;
            }
#pragma unroll
            for (int o = 16; o; o >>= 1) acc += __shfl_xor_sync(0xffffffffu, acc, o);
            if (lane == 0) sc[t * SEQ + s] = acc;
        }
        __syncthreads();

        if (w < 4) {
            float e = (lane < SEQ) ? __expf(sc[w * SEQ + lane]) : 0.f;
            float sum = e;
#pragma unroll
            for (int o = 16; o; o >>= 1) sum += __shfl_xor_sync(0xffffffffu, sum, o);
            if (lane < SEQ)
                attn_out[(size_t)b * TT * SEQ + (size_t)(tc + w) * SEQ + lane] =
                    __fdividef(e, sum);
        }
        __syncthreads();
    }
}

// ---------------- deferred batched ctx pass ----------------
#define CTXB_SMEM ((SEQ * HD + TT * SEQ + SEQ) * 4)
__global__ __launch_bounds__(256)
void ctx_batch_k(const float* __restrict__ ctxw,
                 const float* __restrict__ encw,
                 const float* __restrict__ aprob,    // attn_base [b][t][s]
                 const float* __restrict__ qa,       // ahp2 at cols 512..1023
                 const float* __restrict__ b_ap,
                 fp16* __restrict__ ah,
                 float* __restrict__ ctxdot)
{
    int b = blockIdx.x;
    int tid = threadIdx.x;
    extern __shared__ float sm[];
    float* cw = sm;
    float* ap = sm + SEQ * HD;
    float* ew = ap + TT * SEQ;

    {
        const float4* src = (const float4*)(ctxw + (size_t)b * SEQ * HD);
        float4* dst = (float4*)cw;
        for (int i = tid; i < SEQ * HD / 4; i += 256) dst[i] = src[i];
    }
    for (int i = tid; i < TT * SEQ; i += 256)
        ap[i] = aprob[(size_t)b * TT * SEQ + i];
    if (tid < SEQ) ew[tid] = encw[(size_t)b * SEQ + tid];
    __syncthreads();

    if (tid < TT) {
        float cd = 0.f;
#pragma unroll
        for (int s = 0; s < SEQ; s++) cd += ap[tid * SEQ + s] * ew[s];
        ctxdot[(size_t)tid * BATCH + b] = cd;
    }

    float bap0 = b_ap[tid], bap1 = b_ap[tid + 256];
    for (int t = 0; t < TT; t++) {
        float a0 = 0.f, a1 = 0.f;
        const float* apt = ap + t * SEQ;
#pragma unroll
        for (int s = 0; s < SEQ; s++) {
            float a = apt[s];
            a0 += a * cw[s * HD + tid];
            a1 += a * cw[s * HD + tid + 256];
        }
        const float* qrow = qa + ((size_t)t * BATCH + b) * 1024 + 512;
        size_t base = (size_t)t * BATCH * HD + (size_t)b * HD;
        ah[base + tid]       = __float2half(tanh_fast(qrow[tid] + a0 + bap0));
        ah[base + tid + 256] = __float2half(tanh_fast(qrow[tid + 256] + a1 + bap1));
    }
}

// ---------------- output mix: warp per (t,b) row ----------------
__global__ void out2_k(const float* __restrict__ logits_all,
                       const float* __restrict__ ctxdot,
                       const int* __restrict__ input_char_ids,
                       const float* __restrict__ attn_base,
                       float* __restrict__ outputs)
{
    int warp = threadIdx.x >> 5, lane = threadIdx.x & 31;
    int row = blockIdx.x * 4 + warp;
    int t = row >> 12;
    int b = row & 4095;
    __shared__ float cbuf[4][VOC];

    for (int k = lane; k < VOC; k += 32) cbuf[warp][k] = 0.f;
    __syncwarp();
    if (lane < SEQ) {
        int id = input_char_ids[(size_t)b * SEQ + lane];
        float a = attn_base[(size_t)b * TT * SEQ + (size_t)t * SEQ + lane];
        atomicAdd(&cbuf[warp][id], a);
    }
    __syncwarp();

    const float* lrow = logits_all + (size_t)row * 121;
    float p = sigmoid_fast(lrow[120] + ctxdot[row]);

    float e[4];
    float sum = 0.f;
#pragma unroll
    for (int j = 0; j < 4; j++) {
        int idx = lane + j * 32;
        e[j] = (idx < VOC) ? __expf(lrow[idx]) : 0.f;
        sum += e[j];
    }
#pragma unroll
    for (int o = 16; o; o >>= 1) sum += __shfl_xor_sync(0xffffffffu, sum, o);
    float inv = __fdividef(1.0f - p, sum);
#pragma unroll
    for (int j = 0; j < 4; j++) {
        int idx = lane + j * 32;
        if (idx < VOC)
            outputs[(size_t)b * TT * VOC + (size_t)t * VOC + idx] =
                inv * e[j] + p * cbuf[warp][idx];
    }
}

// ---------------- host ----------------
#define SYM(p, s) cudaGetSymbolAddress((void**)&(p), s)
#define SM128 40960
#define SM64  30720

extern "C" void kernel_launch(void* const* d_in, const int* in_sizes, int n_in,
                              void* d_out, int out_size)
{
    (void)in_sizes; (void)n_in; (void)out_size;
    const float* enc        = (const float*)d_in[0];
    const float* enc_final  = (const float*)d_in[1];
    const int*   tgt        = (const int*)d_in[2];
    const int*   input_ids  = (const int*)d_in[3];
    const float* embed      = (const float*)d_in[4];
    const float* W_init     = (const float*)d_in[5];
    const float* b_init     = (const float*)d_in[6];
    const float* W_ih       = (const float*)d_in[7];
    const float* W_hh       = (const float*)d_in[8];
    const float* b_ih       = (const float*)d_in[9];
    const float* b_hh       = (const float*)d_in[10];
    const float* W_enc_attn = (const float*)d_in[11];
    const float* W_dec_attn = (const float*)d_in[12];
    const float* b_attn     = (const float*)d_in[13];
    const float* v_attn     = (const float*)d_in[14];
    const float* W_ap       = (const float*)d_in[15];
    const float* b_ap       = (const float*)d_in[16];
    const float* W_out      = (const float*)d_in[17];
    const float* b_out      = (const float*)d_in[18];
    const float* w_copy     = (const float*)d_in[19];
    const float* b_copy     = (const float*)d_in[20];

    float* out = (float*)d_out;
    float* outputs   = out;
    float* attn_base = out + (size_t)BATCH * TT * VOC;

    fp16 *ench, *ef, *wg, *wqa, *we, *wapc, *woc, *wi, *h_all, *ah_all;
    float *encproj, *ctxwp, *encw, *embproj, *bqa, *boc, *cst;
    float *qa, *logits_all, *ctxdot;
    SYM(ench, g_ench); SYM(ef, g_ef);
    SYM(encproj, g_encproj); SYM(ctxwp, g_ctxw); SYM(encw, g_encw);
    SYM(embproj, g_embproj);
    SYM(wg, g_wg);     SYM(wqa, g_wqa); SYM(bqa, g_bqa);
    SYM(we, g_we);     SYM(wapc, g_wapc);
    SYM(woc, g_woc);   SYM(boc, g_boc);
    SYM(wi, g_wi);
    SYM(h_all, g_h_all);
    SYM(cst, g_c);     SYM(qa, g_qa);
    SYM(ah_all, g_ah_all);
    SYM(logits_all, g_logits_all); SYM(ctxdot, g_ctxdot);

    cudaFuncSetAttribute(mma_gemm_k<128, false>,
                         cudaFuncAttributeMaxDynamicSharedMemorySize, SM128);
    cudaFuncSetAttribute(mma_gemm_k<64, true>,
                         cudaFuncAttributeMaxDynamicSharedMemorySize, SM64);
    cudaFuncSetAttribute(comb_cell_k,
                         cudaFuncAttributeMaxDynamicSharedMemorySize, SM128);
    cudaFuncSetAttribute(attn_batch_k,
                         cudaFuncAttributeMaxDynamicSharedMemorySize, ATT_SMEM);
    cudaFuncSetAttribute(ctx_batch_k,
                         cudaFuncAttributeMaxDynamicSharedMemorySize, CTXB_SMEM);

    // ---- prep ----
    conv_h_k<<<4096, 256>>>(enc, ench, (size_t)BATCH * SEQ * HE);
    conv_h_k<<<2048, 256>>>(enc_final, ef, (size_t)BATCH * HE);
    embproj_k<<<dim3(16, VOC), 128>>>(embed, W_ih, b_ih, b_hh, embproj);
    prep_wg_k<<<1024, 256>>>(W_hh, wg);
    prep_wqa_k<<<1024, 256>>>(W_dec_attn, W_ap, b_attn, wqa, bqa);
    transpose_h_k<<<1024, 256>>>(W_enc_attn, we, HE, HD);
    prep_wapc_k<<<1024, 256>>>(W_ap, wapc);
    prep_outw_k<<<256, 256>>>(W_out, b_out, w_copy, b_copy, woc, boc);
    conv_h_k<<<1024, 256>>>(W_init, wi, (size_t)HD * HE);
    encw_k<<<BATCH * SEQ, 128>>>(enc, w_copy, encw);
    zero_c_k<<<(BATCH * HD + 255) / 256, 256>>>(cst);

    // h_all[0] = enc_final @ W_init^T + b_init
    mma_gemm_k<64, true><<<dim3(8, 32), 256, SM64>>>(
        ef, HE, wi, HE, b_init,
        nullptr, h_all, HE, HD);
    // enc_proj = enc @ W_enc_attn ; ctxw = enc @ W_ap[:,512:]^T
    mma_gemm_k<128, false><<<dim3(4, 768), 256, SM128>>>(
        ench, HE, we, HE, nullptr,
        encproj, nullptr, HE, HD);
    mma_gemm_k<128, false><<<dim3(4, 768), 256, SM128>>>(
        ench, HE, wapc, HE, nullptr,
        ctxwp, nullptr, HE, HD);

    // serial recurrence: ONLY the gates GEMM + cell per step
    for (int t = 0; t < TT; t++) {
        size_t off = (size_t)t * BATCH * HD;
        comb_cell_k<<<dim3(16, 32), 256, SM128>>>(
            h_all + off, wg, embproj, tgt,
            cst, h_all + off + (size_t)BATCH * HD, t);
    }

    // deferred: [q | ahp2] for ALL steps: M = T*B, N = 1024, K = 512
    mma_gemm_k<128, false><<<dim3(8, (TT * BATCH) / 128), 256, SM128>>>(
        h_all + (size_t)BATCH * HD, HD, wqa, HD, bqa,
        qa, nullptr, HD, 1024);

    // batched attention over all steps (encproj staged once per b)
    attn_batch_k<<<BATCH, 256, ATT_SMEM>>>(encproj, qa, v_attn, attn_base);

    // batched ctx contraction + ah finalize + ctxdot
    ctx_batch_k<<<BATCH, 256, CTXB_SMEM>>>(
        ctxwp, encw, attn_base, qa, b_ap, ah_all, ctxdot);

    // deferred logits+copy GEMM: M = T*B, N = 121, K = 512
    mma_gemm_k<128, false><<<dim3(1, (TT * BATCH) / 128), 256, SM128>>>(
        ah_all, HD, woc, HD, boc,
        logits_all, nullptr, HD, 121);
    out2_k<<<TT * BATCH / 4, 128>>>(logits_all, ctxdot, input_ids, attn_base, outputs);
}